// round 3
// baseline (speedup 1.0000x reference)
#include <cuda_runtime.h>

#define B_   64
#define NGF  256
#define S_   2048
#define ENCH 512
#define ZD   64
#define DECH 256

#define TS 128          // s-rows per block tile
#define TH 64           // h chunk
#define KT 32           // k tile for gemm1
#define NTILES (S_/TS)  // 16

typedef unsigned long long u64t;

__device__ float g_w[B_*NGF];            // [B,256] masked row sums
__device__ float g_c[B_*ENCH];           // [B,512] c_b = w@W1[256:] + b1
__device__ float g_zpart[B_*NTILES*ZD];  // per-(b,tile) partial z

// ---- f32x2 helpers -------------------------------------------------------
__device__ __forceinline__ u64t ffma2(u64t a, u64t b, u64t c) {
    u64t d;
    asm("fma.rn.f32x2 %0, %1, %2, %3;" : "=l"(d) : "l"(a), "l"(b), "l"(c));
    return d;
}
__device__ __forceinline__ u64t pack2(float lo, float hi) {
    u64t d;
    asm("mov.b64 %0, {%1, %2};" : "=l"(d) : "f"(lo), "f"(hi));
    return d;
}
__device__ __forceinline__ void unpack2(u64t v, float& lo, float& hi) {
    asm("mov.b64 {%0, %1}, %2;" : "=f"(lo), "=f"(hi) : "l"(v));
}

// ---------------------------------------------------------------------------
// Kernel A: w[b,g] = sum_{s<len[b]} u[b,g,s].  One warp per row.
// ---------------------------------------------------------------------------
__global__ void rowsum_kernel(const float* __restrict__ u,
                              const int* __restrict__ lengths) {
    int warp = (blockIdx.x * blockDim.x + threadIdx.x) >> 5;
    int lane = threadIdx.x & 31;
    if (warp >= B_ * NGF) return;
    int b = warp >> 8;
    int len = lengths[b];
    const float* row = u + (size_t)warp * S_;
    float sum = 0.f;
    for (int s = lane; s < len; s += 32) sum += row[s];
    #pragma unroll
    for (int o = 16; o > 0; o >>= 1) sum += __shfl_down_sync(0xffffffffu, sum, o);
    if (lane == 0) g_w[warp] = sum;
}

// ---------------------------------------------------------------------------
// Kernel B: c[b,h] = b1[h] + sum_g w[b,g] * W1[256+g, h].
// ---------------------------------------------------------------------------
__global__ void cvec_kernel(const float* __restrict__ W1,
                            const float* __restrict__ b1) {
    __shared__ float wsh[NGF];
    int b = blockIdx.x;
    int h = threadIdx.x;          // 512 threads
    if (h < NGF) wsh[h] = g_w[b * NGF + h];
    __syncthreads();
    float acc = b1[h];
    const float* Wp = W1 + (size_t)NGF * ENCH + h;
    #pragma unroll 8
    for (int g = 0; g < NGF; g++) acc = fmaf(wsh[g], Wp[(size_t)g * ENCH], acc);
    g_c[b * ENCH + h] = acc;
}

// ---------------------------------------------------------------------------
// Kernel C (main): per (b, s-tile of 128) block, 256 threads.
// Micro-tile 8s x 4h per thread; s-rows packed as f32x2 pairs; weight tiles
// duplicated in smem so the splat operand comes from LDS.128 directly.
// ---------------------------------------------------------------------------
__global__ void __launch_bounds__(256)
main_kernel(const float* __restrict__ u, const int* __restrict__ lengths,
            const float* __restrict__ W1, const float* __restrict__ W2,
            const float* __restrict__ b2) {
    extern __shared__ float smem[];
    float* u_s  = smem;                      // [256][128]        128 KB
    float* w1d  = u_s + NGF * TS;            // [32][128] dup      16 KB
    float* h_t  = w1d + KT * (2 * TH);       // [64][132]          33 KB
    float* w2d  = h_t + TH * (TS + 4);       // [64][128] dup      32 KB
    float* red  = w2d + TH * (2 * ZD);       // [16][68]          4.3 KB

    int b = blockIdx.y, tile = blockIdx.x;
    int len = lengths[b];
    int s0 = tile * TS;
    if (s0 >= len) return;                   // uniform per block

    int tid = threadIdx.x;
    int tx = tid & 15, ty = tid >> 4;
    int srow = ty * 8, hcol = tx * 4, zcol = tx * 4;

    // ---- load u tile: u[b, g, s0..s0+127] -> u_s[g][s] (layout matches) ----
    const float* ub = u + ((size_t)b * NGF) * S_ + s0;
    #pragma unroll
    for (int i = tid; i < NGF * (TS / 4); i += 256) {   // 32 iters/thread
        int g = i >> 5, q = i & 31;
        *(float4*)&u_s[g * TS + q * 4] = *(const float4*)(ub + (size_t)g * S_ + q * 4);
    }

    u64t zacc[4][4];
    #pragma unroll
    for (int i = 0; i < 4; i++)
        #pragma unroll
        for (int j = 0; j < 4; j++) zacc[i][j] = 0ull;

    const float* cb = g_c + b * ENCH;
    __syncthreads();   // u_s ready

    for (int hc = 0; hc < ENCH; hc += TH) {
        u64t acc[4][4];
        #pragma unroll
        for (int i = 0; i < 4; i++)
            #pragma unroll
            for (int j = 0; j < 4; j++) acc[i][j] = 0ull;

        // ================= GEMM1 over K=256 in KT tiles ====================
        for (int k0 = 0; k0 < NGF; k0 += KT) {
            // fill w1d duplicated: w1d[kk][2h],[2h+1] = W1[k0+kk][hc+h]
            {
                int kk = tid >> 3, hq = tid & 7;            // 32 x 8
                const float* src = &W1[(size_t)(k0 + kk) * ENCH + hc + hq * 8];
                float4 a = *(const float4*)src;
                float4 c = *(const float4*)(src + 4);
                float* dst = &w1d[kk * 128 + hq * 16];
                *(float4*)(dst + 0)  = make_float4(a.x, a.x, a.y, a.y);
                *(float4*)(dst + 4)  = make_float4(a.z, a.z, a.w, a.w);
                *(float4*)(dst + 8)  = make_float4(c.x, c.x, c.y, c.y);
                *(float4*)(dst + 12) = make_float4(c.z, c.z, c.w, c.w);
            }
            __syncthreads();
            #pragma unroll 8
            for (int kk = 0; kk < KT; kk++) {
                const float* ur = &u_s[(k0 + kk) * TS + srow];
                ulonglong2 a01 = *(const ulonglong2*)ur;        // (s0,s1)(s2,s3)
                ulonglong2 a23 = *(const ulonglong2*)(ur + 4);  // (s4,s5)(s6,s7)
                const float* br = &w1d[kk * 128 + 8 * tx];
                ulonglong2 b01 = *(const ulonglong2*)br;        // splat b0, b1
                ulonglong2 b23 = *(const ulonglong2*)(br + 4);  // splat b2, b3
                u64t av[4] = {a01.x, a01.y, a23.x, a23.y};
                u64t bv[4] = {b01.x, b01.y, b23.x, b23.y};
                #pragma unroll
                for (int i = 0; i < 4; i++)
                    #pragma unroll
                    for (int j = 0; j < 4; j++)
                        acc[i][j] = ffma2(av[i], bv[j], acc[i][j]);
            }
            __syncthreads();
        }

        // fill w2d duplicated while acc is live: w2d[k][2z] = W2[hc+k][z]
        {
            int k = tid >> 2, zq = tid & 3;                 // 64 x 4 (16 z each)
            const float* src = &W2[(size_t)(hc + k) * ZD + zq * 16];
            float* dst = &w2d[k * 128 + zq * 32];
            #pragma unroll
            for (int p = 0; p < 4; p++) {
                float4 a = *(const float4*)(src + p * 4);
                *(float4*)(dst + p * 8 + 0) = make_float4(a.x, a.x, a.y, a.y);
                *(float4*)(dst + p * 8 + 4) = make_float4(a.z, a.z, a.w, a.w);
            }
        }

        // relu(+c_b) -> h_t transposed [h][s] so GEMM2 a-pairs are contiguous
        #pragma unroll
        for (int j = 0; j < 4; j++) {
            float c = cb[hc + hcol + j];
            float r[8];
            #pragma unroll
            for (int i = 0; i < 4; i++) {
                float lo, hi;
                unpack2(acc[i][j], lo, hi);
                r[2 * i]     = fmaxf(lo + c, 0.f);
                r[2 * i + 1] = fmaxf(hi + c, 0.f);
            }
            float* dst = &h_t[(hcol + j) * (TS + 4) + srow];
            *(float4*)(dst + 0) = make_float4(r[0], r[1], r[2], r[3]);
            *(float4*)(dst + 4) = make_float4(r[4], r[5], r[6], r[7]);
        }
        __syncthreads();

        // ================= GEMM2 partial: zacc += H_chunk @ W2_chunk =======
        #pragma unroll 8
        for (int k = 0; k < TH; k++) {
            const float* ar = &h_t[k * (TS + 4) + srow];
            ulonglong2 a01 = *(const ulonglong2*)ar;
            ulonglong2 a23 = *(const ulonglong2*)(ar + 4);
            const float* br = &w2d[k * 128 + 8 * tx];
            ulonglong2 b01 = *(const ulonglong2*)br;
            ulonglong2 b23 = *(const ulonglong2*)(br + 4);
            u64t av[4] = {a01.x, a01.y, a23.x, a23.y};
            u64t bv[4] = {b01.x, b01.y, b23.x, b23.y};
            #pragma unroll
            for (int i = 0; i < 4; i++)
                #pragma unroll
                for (int j = 0; j < 4; j++)
                    zacc[i][j] = ffma2(av[i], bv[j], zacc[i][j]);
        }
        __syncthreads();   // h_t/w2d consumed before next chunk overwrites
    }

    // ---- epilogue: relu(z + b2), mask s >= len, sum the 8 rows ----
    float part[4] = {0.f, 0.f, 0.f, 0.f};
    #pragma unroll
    for (int j = 0; j < 4; j++) {
        float b2v = b2[zcol + j];
        #pragma unroll
        for (int i = 0; i < 4; i++) {
            float lo, hi;
            unpack2(zacc[i][j], lo, hi);
            int s = s0 + srow + 2 * i;
            if (s < len)     part[j] += fmaxf(lo + b2v, 0.f);
            if (s + 1 < len) part[j] += fmaxf(hi + b2v, 0.f);
        }
    }
    #pragma unroll
    for (int j = 0; j < 4; j++) red[ty * (ZD + 4) + zcol + j] = part[j];
    __syncthreads();
    if (tid < ZD) {
        float s = 0.f;
        #pragma unroll
        for (int t = 0; t < 16; t++) s += red[t * (ZD + 4) + tid];
        g_zpart[(b * NTILES + tile) * ZD + tid] = s;
    }
}

// ---------------------------------------------------------------------------
// Kernel D: z = sum of partials; d = relu(z@W3+b3); y = d@W4 + b4.
// ---------------------------------------------------------------------------
__global__ void tail_kernel(const int* __restrict__ lengths,
                            const float* __restrict__ W3, const float* __restrict__ b3,
                            const float* __restrict__ W4, const float* __restrict__ b4,
                            float* __restrict__ y) {
    __shared__ float z_b[ZD];
    __shared__ float redc[DECH];
    int b = blockIdx.x;
    int tid = threadIdx.x;
    int len = lengths[b];
    int ntiles = (len + TS - 1) / TS;
    if (tid < ZD) {
        float s = 0.f;
        for (int t = 0; t < ntiles; t++) s += g_zpart[(b * NTILES + t) * ZD + tid];
        z_b[tid] = s;
    }
    __syncthreads();
    float acc = b3[tid];
    #pragma unroll 8
    for (int k = 0; k < ZD; k++) acc = fmaf(z_b[k], W3[k * DECH + tid], acc);
    redc[tid] = fmaxf(acc, 0.f) * W4[tid];
    __syncthreads();
    #pragma unroll
    for (int o = DECH / 2; o > 0; o >>= 1) {
        if (tid < o) redc[tid] += redc[tid + o];
        __syncthreads();
    }
    if (tid == 0) y[b] = redc[0] + b4[0];
}

// ---------------------------------------------------------------------------
extern "C" void kernel_launch(void* const* d_in, const int* in_sizes, int n_in,
                              void* d_out, int out_size) {
    const float* u       = (const float*)d_in[0];
    const int*   lengths = (const int*)  d_in[1];
    const float* W1      = (const float*)d_in[2];
    const float* b1      = (const float*)d_in[3];
    const float* W2      = (const float*)d_in[4];
    const float* b2      = (const float*)d_in[5];
    const float* W3      = (const float*)d_in[6];
    const float* b3      = (const float*)d_in[7];
    const float* W4      = (const float*)d_in[8];
    const float* b4      = (const float*)d_in[9];
    float* y = (float*)d_out;

    size_t smem = (size_t)(NGF * TS + KT * 2 * TH + TH * (TS + 4) + TH * 2 * ZD
                           + 16 * (ZD + 4)) * sizeof(float);
    static int smem_set = 0;
    if (!smem_set) {
        cudaFuncSetAttribute((const void*)main_kernel,
                             cudaFuncAttributeMaxDynamicSharedMemorySize, (int)smem);
        smem_set = 1;
    }

    rowsum_kernel<<<(B_ * NGF) / 8, 256>>>(u, lengths);
    cvec_kernel<<<B_, ENCH>>>(W1, b1);

    dim3 grid(NTILES, B_);
    main_kernel<<<grid, 256, smem>>>(u, lengths, W1, W2, b2);

    tail_kernel<<<B_, DECH>>>(lengths, W3, b3, W4, b4, y);
}

// round 6
// speedup vs baseline: 4.2471x; 4.2471x over previous
#include <cuda_runtime.h>
#include <cuda_bf16.h>

typedef unsigned int u32;
typedef unsigned long long u64;

#define B_   64
#define NGF  256
#define S_   2048
#define ENCH 512
#define ZD   64
#define DECH 256
#define TS   128
#define NTILES 16

// ---- smem byte offsets ----
#define U_HI   0         // [256 g][128 s] bf16  64KB
#define U_LO   65536
#define A1_HI  131072    // [64 h][256 g] bf16   32KB
#define A1_LO  163840
#define W2_HI  131072    // overlay on A1 (after GEMM1 done): [64 z][64 h] 8KB
#define W2_LO  139264
#define HT_HI  196608    // [64 h][128 s] bf16   16KB
#define HT_LO  212992
#define RED_O  229376    // 128 floats
#define SMEM_SZ 229888

__device__ float g_w[B_*NGF];
__device__ float g_c[B_*ENCH];
__device__ float g_zpart[B_*NTILES*ZD];
__device__ __nv_bfloat16 g_w1t_hi[ENCH*NGF];   // [h][g] = hi(W1[g][h])
__device__ __nv_bfloat16 g_w1t_lo[ENCH*NGF];
__device__ __nv_bfloat16 g_w2t_hi[ZD*ENCH];    // [z][h] = hi(W2[h][z])
__device__ __nv_bfloat16 g_w2t_lo[ZD*ENCH];

// ---- helpers ---------------------------------------------------------------
__device__ __forceinline__ u32 smem_u32(const void* p) {
    u32 a;
    asm("{ .reg .u64 t; cvta.to.shared.u64 t, %1; cvt.u32.u64 %0, t; }"
        : "=r"(a) : "l"(p));
    return a;
}
__device__ __forceinline__ void ldsm4(u32* r, u32 addr) {
    asm volatile("ldmatrix.sync.aligned.m8n8.x4.shared.b16 {%0,%1,%2,%3}, [%4];"
        : "=r"(r[0]), "=r"(r[1]), "=r"(r[2]), "=r"(r[3]) : "r"(addr));
}
__device__ __forceinline__ void ldsm4t(u32* r, u32 addr) {
    asm volatile("ldmatrix.sync.aligned.m8n8.x4.trans.shared.b16 {%0,%1,%2,%3}, [%4];"
        : "=r"(r[0]), "=r"(r[1]), "=r"(r[2]), "=r"(r[3]) : "r"(addr));
}
__device__ __forceinline__ void mma_bf(float* c, const u32* a, u32 b0, u32 b1) {
    asm volatile("mma.sync.aligned.m16n8k16.row.col.f32.bf16.bf16.f32 "
        "{%0,%1,%2,%3}, {%4,%5,%6,%7}, {%8,%9}, {%0,%1,%2,%3};"
        : "+f"(c[0]), "+f"(c[1]), "+f"(c[2]), "+f"(c[3])
        : "r"(a[0]), "r"(a[1]), "r"(a[2]), "r"(a[3]), "r"(b0), "r"(b1));
}
// pack (v0->low, v1->high) hi/lo bf16 splits
__device__ __forceinline__ void split2(float v0, float v1, u32& ph, u32& pl) {
    asm("cvt.rn.bf16x2.f32 %0, %1, %2;" : "=r"(ph) : "f"(v1), "f"(v0));
    float h0 = __uint_as_float(ph << 16);
    float h1 = __uint_as_float(ph & 0xffff0000u);
    float l0 = v0 - h0, l1 = v1 - h1;
    asm("cvt.rn.bf16x2.f32 %0, %1, %2;" : "=r"(pl) : "f"(l1), "f"(l0));
}

// ---------------------------------------------------------------------------
// Prep kernels
// ---------------------------------------------------------------------------
__global__ void rowsum_kernel(const float* __restrict__ u,
                              const int* __restrict__ lengths) {
    int warp = (blockIdx.x * blockDim.x + threadIdx.x) >> 5;
    int lane = threadIdx.x & 31;
    if (warp >= B_ * NGF) return;
    int b = warp >> 8;
    int len = lengths[b];
    const float* row = u + (size_t)warp * S_;
    float sum = 0.f;
    for (int s = lane; s < len; s += 32) sum += row[s];
    #pragma unroll
    for (int o = 16; o > 0; o >>= 1) sum += __shfl_down_sync(0xffffffffu, sum, o);
    if (lane == 0) g_w[warp] = sum;
}

__global__ void cvec_kernel(const float* __restrict__ W1,
                            const float* __restrict__ b1) {
    __shared__ float wsh[NGF];
    int b = blockIdx.x;
    int h = threadIdx.x;          // 512 threads
    if (h < NGF) wsh[h] = g_w[b * NGF + h];
    __syncthreads();
    float acc = b1[h];
    const float* Wp = W1 + (size_t)NGF * ENCH + h;
    #pragma unroll 8
    for (int g = 0; g < NGF; g++) acc = fmaf(wsh[g], Wp[(size_t)g * ENCH], acc);
    g_c[b * ENCH + h] = acc;
}

__global__ void prep_w1t(const float* __restrict__ W1) {
    int idx = blockIdx.x * 256 + threadIdx.x;     // 512*256
    int h = idx >> 8, g = idx & 255;
    float x = W1[(size_t)g * ENCH + h];
    __nv_bfloat16 hi = __float2bfloat16(x);
    g_w1t_hi[h * NGF + g] = hi;
    g_w1t_lo[h * NGF + g] = __float2bfloat16(x - __bfloat162float(hi));
}

__global__ void prep_w2t(const float* __restrict__ W2) {
    int idx = blockIdx.x * 256 + threadIdx.x;     // 64*512
    int z = idx >> 9, h = idx & 511;
    float x = W2[(size_t)h * ZD + z];
    __nv_bfloat16 hi = __float2bfloat16(x);
    g_w2t_hi[z * ENCH + h] = hi;
    g_w2t_lo[z * ENCH + h] = __float2bfloat16(x - __bfloat162float(hi));
}

// ---------------------------------------------------------------------------
// Main HMMA kernel: per (b, 128-s tile). 256 threads = 8 warps (4m x 2n).
// Computes H^T = W1T@u (per 64-h chunk) then Z^T += W2T_chunk @ H^T.
// ---------------------------------------------------------------------------
__global__ void __launch_bounds__(256)
main_kernel(const float* __restrict__ u, const int* __restrict__ lengths,
            const float* __restrict__ b2) {
    extern __shared__ char smem[];
    u32 sb = smem_u32(smem);
    int b = blockIdx.y, tile = blockIdx.x;
    int len = lengths[b];
    int s0 = tile * TS;
    if (s0 >= len) return;

    int tid = threadIdx.x;
    int lane = tid & 31;
    int wq = tid >> 5;
    int wm = wq >> 1;          // m-quadrant (rows 16*wm..)
    int wn = wq & 1;           // n-half (s cols 64*wn..)
    int gid = lane >> 2, tq = lane & 3;

    // ---- load u tile fp32, split -> U_HI/U_LO [g][s] swizzled ----
    const float* ub = u + ((size_t)b * NGF) * S_ + s0;
    #pragma unroll 4
    for (int it = 0; it < 32; it++) {
        int i = tid + 256 * it;
        int g = i >> 5, q = i & 31;
        float4 v = *(const float4*)(ub + (size_t)g * S_ + q * 4);
        u32 ph0, pl0, ph1, pl1;
        split2(v.x, v.y, ph0, pl0);
        split2(v.z, v.w, ph1, pl1);
        u32 off = (u32)(g * 256 + (((q >> 1) ^ (g & 7)) << 4) + ((q & 1) << 3));
        *(uint2*)(smem + U_HI + off) = make_uint2(ph0, ph1);
        *(uint2*)(smem + U_LO + off) = make_uint2(pl0, pl1);
    }
    __syncthreads();

    float zc[8][4];
    #pragma unroll
    for (int j = 0; j < 8; j++)
        #pragma unroll
        for (int r = 0; r < 4; r++) zc[j][r] = 0.f;

    const float* cb = g_c + b * ENCH;
    int arow = 16 * wm + (lane & 15);
    int asel = lane >> 4;

    for (int hc = 0; hc < 8; hc++) {
        // ---- load A1 slice (W1T rows hc*64..+63, all 256 g) hi+lo ----
        #pragma unroll
        for (int it = 0; it < 8; it++) {
            int idx = tid + 256 * it;          // 2048 uint4 per plane
            int h = idx >> 5, c = idx & 31;
            u32 off = (u32)(h * 512 + ((c ^ (h & 7)) << 4));
            const __nv_bfloat16* s1 = g_w1t_hi + ((size_t)(hc * 64 + h)) * NGF + c * 8;
            const __nv_bfloat16* s2 = g_w1t_lo + ((size_t)(hc * 64 + h)) * NGF + c * 8;
            *(uint4*)(smem + A1_HI + off) = *(const uint4*)s1;
            *(uint4*)(smem + A1_LO + off) = *(const uint4*)s2;
        }
        __syncthreads();

        float hacc[8][4];
        #pragma unroll
        for (int j = 0; j < 8; j++)
            #pragma unroll
            for (int r = 0; r < 4; r++) hacc[j][r] = 0.f;

        // ---- GEMM1: K = 256 (16 k16-steps) ----
        for (int k = 0; k < 16; k++) {
            u32 a_hi[4], a_lo[4];
            u32 ach = (u32)(((2 * k + asel) ^ (arow & 7)) << 4);
            ldsm4(a_hi, sb + A1_HI + arow * 512 + ach);
            ldsm4(a_lo, sb + A1_LO + arow * 512 + ach);
            int brow = 16 * k + (lane & 15);
            #pragma unroll
            for (int j = 0; j < 4; j++) {
                u32 bh[4], bl[4];
                u32 bc = (u32)((((8 * wn + 2 * j + asel)) ^ (brow & 7)) << 4);
                u32 boff = (u32)(brow * 256) + bc;
                ldsm4t(bh, sb + U_HI + boff);
                ldsm4t(bl, sb + U_LO + boff);
                mma_bf(hacc[2 * j],     a_hi, bh[0], bh[1]);
                mma_bf(hacc[2 * j + 1], a_hi, bh[2], bh[3]);
                mma_bf(hacc[2 * j],     a_hi, bl[0], bl[1]);
                mma_bf(hacc[2 * j + 1], a_hi, bl[2], bl[3]);
                mma_bf(hacc[2 * j],     a_lo, bh[0], bh[1]);
                mma_bf(hacc[2 * j + 1], a_lo, bh[2], bh[3]);
            }
        }
        __syncthreads();   // all warps done reading A1 before W2 overlay

        // ---- epilogue: bias+relu, split, store H^T [hloc][s] ----
        {
            int h0g = hc * 64 + 16 * wm + gid;
            float bia0 = cb[h0g], bia1 = cb[h0g + 8];
            int hl0 = 16 * wm + gid, hl1 = hl0 + 8;
            #pragma unroll
            for (int j = 0; j < 8; j++) {
                int sbse = wn * 64 + j * 8;
                float v00 = fmaxf(hacc[j][0] + bia0, 0.f);
                float v01 = fmaxf(hacc[j][1] + bia0, 0.f);
                float v10 = fmaxf(hacc[j][2] + bia1, 0.f);
                float v11 = fmaxf(hacc[j][3] + bia1, 0.f);
                u32 ph, pl;
                split2(v00, v01, ph, pl);
                u32 off0 = (u32)(hl0 * 256 + (((sbse >> 3) ^ (hl0 & 7)) << 4) + 4 * tq);
                *(u32*)(smem + HT_HI + off0) = ph;
                *(u32*)(smem + HT_LO + off0) = pl;
                split2(v10, v11, ph, pl);
                u32 off1 = (u32)(hl1 * 256 + (((sbse >> 3) ^ (hl1 & 7)) << 4) + 4 * tq);
                *(u32*)(smem + HT_HI + off1) = ph;
                *(u32*)(smem + HT_LO + off1) = pl;
            }
        }
        // ---- load W2T slice [64 z][64 h-chunk] hi+lo (overlay) ----
        #pragma unroll
        for (int it = 0; it < 2; it++) {
            int idx = tid + 256 * it;          // 512 uint4 per plane
            int z = idx >> 3, c = idx & 7;
            u32 off = (u32)(z * 128 + ((c ^ (z & 7)) << 4));
            *(uint4*)(smem + W2_HI + off) =
                *(const uint4*)(g_w2t_hi + (size_t)z * ENCH + hc * 64 + c * 8);
            *(uint4*)(smem + W2_LO + off) =
                *(const uint4*)(g_w2t_lo + (size_t)z * ENCH + hc * 64 + c * 8);
        }
        __syncthreads();

        // ---- GEMM2 partial: K = 64 (4 k16-steps) ----
        for (int k2 = 0; k2 < 4; k2++) {
            u32 a_hi[4], a_lo[4];
            u32 ach = (u32)(((2 * k2 + asel) ^ (arow & 7)) << 4);
            ldsm4(a_hi, sb + W2_HI + arow * 128 + ach);
            ldsm4(a_lo, sb + W2_LO + arow * 128 + ach);
            int brow = 16 * k2 + (lane & 15);
            #pragma unroll
            for (int j = 0; j < 4; j++) {
                u32 bh[4], bl[4];
                u32 bc = (u32)((((8 * wn + 2 * j + asel)) ^ (brow & 7)) << 4);
                u32 boff = (u32)(brow * 256) + bc;
                ldsm4t(bh, sb + HT_HI + boff);
                ldsm4t(bl, sb + HT_LO + boff);
                mma_bf(zc[2 * j],     a_hi, bh[0], bh[1]);
                mma_bf(zc[2 * j + 1], a_hi, bh[2], bh[3]);
                mma_bf(zc[2 * j],     a_hi, bl[0], bl[1]);
                mma_bf(zc[2 * j + 1], a_hi, bl[2], bl[3]);
                mma_bf(zc[2 * j],     a_lo, bh[0], bh[1]);
                mma_bf(zc[2 * j + 1], a_lo, bh[2], bh[3]);
            }
        }
        __syncthreads();   // Ht/W2 consumed; safe to overwrite next chunk
    }

    // ---- final: bias+relu+mask, reduce over s ----
    float* red = (float*)(smem + RED_O);
    {
        int z0 = 16 * wm + gid, z1 = z0 + 8;
        float bz0 = b2[z0], bz1 = b2[z1];
        float p0 = 0.f, p1 = 0.f;
        #pragma unroll
        for (int j = 0; j < 8; j++) {
            int sa = s0 + wn * 64 + j * 8 + 2 * tq;
            if (sa < len) {
                p0 += fmaxf(zc[j][0] + bz0, 0.f);
                p1 += fmaxf(zc[j][2] + bz1, 0.f);
            }
            if (sa + 1 < len) {
                p0 += fmaxf(zc[j][1] + bz0, 0.f);
                p1 += fmaxf(zc[j][3] + bz1, 0.f);
            }
        }
        p0 += __shfl_xor_sync(0xffffffffu, p0, 1);
        p0 += __shfl_xor_sync(0xffffffffu, p0, 2);
        p1 += __shfl_xor_sync(0xffffffffu, p1, 1);
        p1 += __shfl_xor_sync(0xffffffffu, p1, 2);
        if (tq == 0) {
            red[wq * 16 + gid]     = p0;
            red[wq * 16 + gid + 8] = p1;
        }
    }
    __syncthreads();
    if (tid < ZD) {
        int zq = tid >> 4, zr = tid & 15;
        g_zpart[(b * NTILES + tile) * ZD + tid] =
            red[(zq * 2) * 16 + zr] + red[(zq * 2 + 1) * 16 + zr];
    }
}

// ---------------------------------------------------------------------------
// Tail: z = sum of partials; d = relu(z@W3+b3); y = d@W4 + b4.
// ---------------------------------------------------------------------------
__global__ void tail_kernel(const int* __restrict__ lengths,
                            const float* __restrict__ W3, const float* __restrict__ b3,
                            const float* __restrict__ W4, const float* __restrict__ b4,
                            float* __restrict__ y) {
    __shared__ float z_b[ZD];
    __shared__ float redc[DECH];
    int b = blockIdx.x;
    int tid = threadIdx.x;
    int len = lengths[b];
    int ntiles = (len + TS - 1) / TS;
    if (tid < ZD) {
        float s = 0.f;
        for (int t = 0; t < ntiles; t++) s += g_zpart[(b * NTILES + t) * ZD + tid];
        z_b[tid] = s;
    }
    __syncthreads();
    float acc = b3[tid];
    #pragma unroll 8
    for (int k = 0; k < ZD; k++) acc = fmaf(z_b[k], W3[k * DECH + tid], acc);
    redc[tid] = fmaxf(acc, 0.f) * W4[tid];
    __syncthreads();
    #pragma unroll
    for (int o = DECH / 2; o > 0; o >>= 1) {
        if (tid < o) redc[tid] += redc[tid + o];
        __syncthreads();
    }
    if (tid == 0) y[b] = redc[0] + b4[0];
}

// ---------------------------------------------------------------------------
extern "C" void kernel_launch(void* const* d_in, const int* in_sizes, int n_in,
                              void* d_out, int out_size) {
    const float* u       = (const float*)d_in[0];
    const int*   lengths = (const int*)  d_in[1];
    const float* W1      = (const float*)d_in[2];
    const float* b1      = (const float*)d_in[3];
    const float* W2      = (const float*)d_in[4];
    const float* b2      = (const float*)d_in[5];
    const float* W3      = (const float*)d_in[6];
    const float* b3      = (const float*)d_in[7];
    const float* W4      = (const float*)d_in[8];
    const float* b4      = (const float*)d_in[9];
    float* y = (float*)d_out;

    static int smem_set = 0;
    if (!smem_set) {
        cudaFuncSetAttribute((const void*)main_kernel,
                             cudaFuncAttributeMaxDynamicSharedMemorySize, SMEM_SZ);
        smem_set = 1;
    }

    rowsum_kernel<<<2048, 256>>>(u, lengths);
    cvec_kernel<<<B_, ENCH>>>(W1, b1);
    prep_w1t<<<512, 256>>>(W1);
    prep_w2t<<<128, 256>>>(W2);

    dim3 grid(NTILES, B_);
    main_kernel<<<grid, 256, SMEM_SZ>>>(u, lengths, b2);

    tail_kernel<<<B_, DECH>>>(lengths, W3, b3, W4, b4, y);
}

// round 7
// speedup vs baseline: 4.3577x; 1.0260x over previous
#include <cuda_runtime.h>
#include <cuda_bf16.h>

typedef unsigned int u32;
typedef unsigned long long u64;

#define B_   64
#define NGF  256
#define S_   2048
#define ENCH 512
#define ZD   64
#define DECH 256
#define TS   128
#define NTILES 16

// ---- smem byte offsets ----
#define U_HI   0         // [256 g][128 s] bf16  64KB
#define U_LO   65536
#define A1_HI  131072    // [64 h][256 g] bf16   32KB
#define A1_LO  163840
#define W2_HI  131072    // overlay on A1 (after GEMM1 done): [64 z][64 h] 8KB
#define W2_LO  139264
#define HT_HI  196608    // [64 h][128 s] bf16   16KB
#define HT_LO  212992
#define RED_O  229376    // 256 floats
#define SMEM_SZ 230400

__device__ float g_w[B_*NGF];
__device__ float g_c[B_*ENCH];
__device__ float g_zpart[B_*NTILES*ZD];
__device__ __nv_bfloat16 g_w1t_hi[ENCH*NGF];   // [h][g] = hi(W1[g][h])
__device__ __nv_bfloat16 g_w1t_lo[ENCH*NGF];
__device__ __nv_bfloat16 g_w2t_hi[ZD*ENCH];    // [z][h] = hi(W2[h][z])
__device__ __nv_bfloat16 g_w2t_lo[ZD*ENCH];

// ---- helpers ---------------------------------------------------------------
__device__ __forceinline__ u32 smem_u32(const void* p) {
    u32 a;
    asm("{ .reg .u64 t; cvta.to.shared.u64 t, %1; cvt.u32.u64 %0, t; }"
        : "=r"(a) : "l"(p));
    return a;
}
__device__ __forceinline__ void ldsm4(u32* r, u32 addr) {
    asm volatile("ldmatrix.sync.aligned.m8n8.x4.shared.b16 {%0,%1,%2,%3}, [%4];"
        : "=r"(r[0]), "=r"(r[1]), "=r"(r[2]), "=r"(r[3]) : "r"(addr));
}
__device__ __forceinline__ void ldsm4t(u32* r, u32 addr) {
    asm volatile("ldmatrix.sync.aligned.m8n8.x4.trans.shared.b16 {%0,%1,%2,%3}, [%4];"
        : "=r"(r[0]), "=r"(r[1]), "=r"(r[2]), "=r"(r[3]) : "r"(addr));
}
__device__ __forceinline__ void mma_bf(float* c, const u32* a, u32 b0, u32 b1) {
    asm volatile("mma.sync.aligned.m16n8k16.row.col.f32.bf16.bf16.f32 "
        "{%0,%1,%2,%3}, {%4,%5,%6,%7}, {%8,%9}, {%0,%1,%2,%3};"
        : "+f"(c[0]), "+f"(c[1]), "+f"(c[2]), "+f"(c[3])
        : "r"(a[0]), "r"(a[1]), "r"(a[2]), "r"(a[3]), "r"(b0), "r"(b1));
}
// pack (v0->low, v1->high) hi/lo bf16 splits
__device__ __forceinline__ void split2(float v0, float v1, u32& ph, u32& pl) {
    asm("cvt.rn.bf16x2.f32 %0, %1, %2;" : "=r"(ph) : "f"(v1), "f"(v0));
    float h0 = __uint_as_float(ph << 16);
    float h1 = __uint_as_float(ph & 0xffff0000u);
    float l0 = v0 - h0, l1 = v1 - h1;
    asm("cvt.rn.bf16x2.f32 %0, %1, %2;" : "=r"(pl) : "f"(l1), "f"(l0));
}

// ---------------------------------------------------------------------------
// Prep kernels
// ---------------------------------------------------------------------------
__global__ void rowsum_kernel(const float* __restrict__ u,
                              const int* __restrict__ lengths) {
    int warp = (blockIdx.x * blockDim.x + threadIdx.x) >> 5;
    int lane = threadIdx.x & 31;
    if (warp >= B_ * NGF) return;
    int b = warp >> 8;
    int len = lengths[b];
    const float* row = u + (size_t)warp * S_;
    float sum = 0.f;
    for (int s = lane; s < len; s += 32) sum += row[s];
    #pragma unroll
    for (int o = 16; o > 0; o >>= 1) sum += __shfl_down_sync(0xffffffffu, sum, o);
    if (lane == 0) g_w[warp] = sum;
}

__global__ void cvec_kernel(const float* __restrict__ W1,
                            const float* __restrict__ b1) {
    __shared__ float wsh[NGF];
    int b = blockIdx.x;
    int h = threadIdx.x;          // 512 threads
    if (h < NGF) wsh[h] = g_w[b * NGF + h];
    __syncthreads();
    float acc = b1[h];
    const float* Wp = W1 + (size_t)NGF * ENCH + h;
    #pragma unroll 8
    for (int g = 0; g < NGF; g++) acc = fmaf(wsh[g], Wp[(size_t)g * ENCH], acc);
    g_c[b * ENCH + h] = acc;
}

__global__ void prep_w1t(const float* __restrict__ W1) {
    int idx = blockIdx.x * 256 + threadIdx.x;     // 512*256
    int h = idx >> 8, g = idx & 255;
    float x = W1[(size_t)g * ENCH + h];
    __nv_bfloat16 hi = __float2bfloat16(x);
    g_w1t_hi[h * NGF + g] = hi;
    g_w1t_lo[h * NGF + g] = __float2bfloat16(x - __bfloat162float(hi));
}

__global__ void prep_w2t(const float* __restrict__ W2) {
    int idx = blockIdx.x * 256 + threadIdx.x;     // 64*512
    int z = idx >> 9, h = idx & 511;
    float x = W2[(size_t)h * ZD + z];
    __nv_bfloat16 hi = __float2bfloat16(x);
    g_w2t_hi[z * ENCH + h] = hi;
    g_w2t_lo[z * ENCH + h] = __float2bfloat16(x - __bfloat162float(hi));
}

// ---------------------------------------------------------------------------
// Main HMMA kernel: per (b, 128-s tile). 512 threads = 16 warps (4m x 4n).
// Computes H^T = W1T@u (per 64-h chunk) then Z^T += W2T_chunk @ H^T.
// ---------------------------------------------------------------------------
__global__ void __launch_bounds__(512)
main_kernel(const float* __restrict__ u, const int* __restrict__ lengths,
            const float* __restrict__ b2) {
    extern __shared__ char smem[];
    u32 sb = smem_u32(smem);
    int b = blockIdx.y, tile = blockIdx.x;
    int len = lengths[b];
    int s0 = tile * TS;
    if (s0 >= len) return;

    int tid = threadIdx.x;
    int lane = tid & 31;
    int wq = tid >> 5;         // 0..15
    int wm = wq >> 2;          // m-quadrant (16 rows each)
    int wn = wq & 3;           // n-quadrant (32 s cols each)
    int gid = lane >> 2, tq = lane & 3;

    // ---- load u tile fp32, split -> U_HI/U_LO [g][s] swizzled ----
    const float* ub = u + ((size_t)b * NGF) * S_ + s0;
    #pragma unroll 4
    for (int it = 0; it < 16; it++) {
        int i = tid + 512 * it;
        int g = i >> 5, q = i & 31;
        float4 v = *(const float4*)(ub + (size_t)g * S_ + q * 4);
        u32 ph0, pl0, ph1, pl1;
        split2(v.x, v.y, ph0, pl0);
        split2(v.z, v.w, ph1, pl1);
        u32 off = (u32)(g * 256 + (((q >> 1) ^ (g & 7)) << 4) + ((q & 1) << 3));
        *(uint2*)(smem + U_HI + off) = make_uint2(ph0, ph1);
        *(uint2*)(smem + U_LO + off) = make_uint2(pl0, pl1);
    }
    __syncthreads();

    float zc[4][4];
    #pragma unroll
    for (int j = 0; j < 4; j++)
        #pragma unroll
        for (int r = 0; r < 4; r++) zc[j][r] = 0.f;

    const float* cb = g_c + b * ENCH;
    int arow = 16 * wm + (lane & 15);
    int asel = lane >> 4;

    for (int hc = 0; hc < 8; hc++) {
        // ---- load A1 slice (W1T rows hc*64..+63, all 256 g) hi+lo ----
        #pragma unroll
        for (int it = 0; it < 4; it++) {
            int idx = tid + 512 * it;          // 2048 uint4 per plane
            int h = idx >> 5, c = idx & 31;
            u32 off = (u32)(h * 512 + ((c ^ (h & 7)) << 4));
            const __nv_bfloat16* s1 = g_w1t_hi + ((size_t)(hc * 64 + h)) * NGF + c * 8;
            const __nv_bfloat16* s2 = g_w1t_lo + ((size_t)(hc * 64 + h)) * NGF + c * 8;
            *(uint4*)(smem + A1_HI + off) = *(const uint4*)s1;
            *(uint4*)(smem + A1_LO + off) = *(const uint4*)s2;
        }
        __syncthreads();

        float hacc[4][4];
        #pragma unroll
        for (int j = 0; j < 4; j++)
            #pragma unroll
            for (int r = 0; r < 4; r++) hacc[j][r] = 0.f;

        // ---- GEMM1: K = 256 (16 k16-steps) ----
        #pragma unroll 4
        for (int k = 0; k < 16; k++) {
            u32 a_hi[4], a_lo[4];
            u32 ach = (u32)(((2 * k + asel) ^ (arow & 7)) << 4);
            ldsm4(a_hi, sb + A1_HI + arow * 512 + ach);
            ldsm4(a_lo, sb + A1_LO + arow * 512 + ach);
            int brow = 16 * k + (lane & 15);
            #pragma unroll
            for (int j = 0; j < 2; j++) {
                u32 bh[4], bl[4];
                u32 bc = (u32)((((4 * wn + 2 * j + asel)) ^ (brow & 7)) << 4);
                u32 boff = (u32)(brow * 256) + bc;
                ldsm4t(bh, sb + U_HI + boff);
                ldsm4t(bl, sb + U_LO + boff);
                mma_bf(hacc[2 * j],     a_hi, bh[0], bh[1]);
                mma_bf(hacc[2 * j + 1], a_hi, bh[2], bh[3]);
                mma_bf(hacc[2 * j],     a_hi, bl[0], bl[1]);
                mma_bf(hacc[2 * j + 1], a_hi, bl[2], bl[3]);
                mma_bf(hacc[2 * j],     a_lo, bh[0], bh[1]);
                mma_bf(hacc[2 * j + 1], a_lo, bh[2], bh[3]);
            }
        }
        __syncthreads();   // all warps done reading A1 before W2 overlay

        // ---- epilogue: bias+relu, split, store H^T [hloc][s] ----
        {
            int h0g = hc * 64 + 16 * wm + gid;
            float bia0 = cb[h0g], bia1 = cb[h0g + 8];
            int hl0 = 16 * wm + gid, hl1 = hl0 + 8;
            #pragma unroll
            for (int j = 0; j < 4; j++) {
                int sbse = wn * 32 + j * 8;
                float v00 = fmaxf(hacc[j][0] + bia0, 0.f);
                float v01 = fmaxf(hacc[j][1] + bia0, 0.f);
                float v10 = fmaxf(hacc[j][2] + bia1, 0.f);
                float v11 = fmaxf(hacc[j][3] + bia1, 0.f);
                u32 ph, pl;
                split2(v00, v01, ph, pl);
                u32 off0 = (u32)(hl0 * 256 + (((sbse >> 3) ^ (hl0 & 7)) << 4) + 4 * tq);
                *(u32*)(smem + HT_HI + off0) = ph;
                *(u32*)(smem + HT_LO + off0) = pl;
                split2(v10, v11, ph, pl);
                u32 off1 = (u32)(hl1 * 256 + (((sbse >> 3) ^ (hl1 & 7)) << 4) + 4 * tq);
                *(u32*)(smem + HT_HI + off1) = ph;
                *(u32*)(smem + HT_LO + off1) = pl;
            }
        }
        // ---- load W2T slice [64 z][64 h-chunk] hi+lo (overlay) ----
        {
            int idx = tid;                     // 512 uint4 per plane
            int z = idx >> 3, c = idx & 7;
            u32 off = (u32)(z * 128 + ((c ^ (z & 7)) << 4));
            *(uint4*)(smem + W2_HI + off) =
                *(const uint4*)(g_w2t_hi + (size_t)z * ENCH + hc * 64 + c * 8);
            *(uint4*)(smem + W2_LO + off) =
                *(const uint4*)(g_w2t_lo + (size_t)z * ENCH + hc * 64 + c * 8);
        }
        __syncthreads();

        // ---- GEMM2 partial: K = 64 (4 k16-steps) ----
        #pragma unroll
        for (int k2 = 0; k2 < 4; k2++) {
            u32 a_hi[4], a_lo[4];
            u32 ach = (u32)(((2 * k2 + asel) ^ (arow & 7)) << 4);
            ldsm4(a_hi, sb + W2_HI + arow * 128 + ach);
            ldsm4(a_lo, sb + W2_LO + arow * 128 + ach);
            int brow = 16 * k2 + (lane & 15);
            #pragma unroll
            for (int j = 0; j < 2; j++) {
                u32 bh[4], bl[4];
                u32 bc = (u32)((((4 * wn + 2 * j + asel)) ^ (brow & 7)) << 4);
                u32 boff = (u32)(brow * 256) + bc;
                ldsm4t(bh, sb + HT_HI + boff);
                ldsm4t(bl, sb + HT_LO + boff);
                mma_bf(zc[2 * j],     a_hi, bh[0], bh[1]);
                mma_bf(zc[2 * j + 1], a_hi, bh[2], bh[3]);
                mma_bf(zc[2 * j],     a_hi, bl[0], bl[1]);
                mma_bf(zc[2 * j + 1], a_hi, bl[2], bl[3]);
                mma_bf(zc[2 * j],     a_lo, bh[0], bh[1]);
                mma_bf(zc[2 * j + 1], a_lo, bh[2], bh[3]);
            }
        }
        __syncthreads();   // Ht/W2 consumed; safe to overwrite next chunk
    }

    // ---- final: bias+relu+mask, reduce over s ----
    float* red = (float*)(smem + RED_O);
    {
        int z0 = 16 * wm + gid, z1 = z0 + 8;
        float bz0 = b2[z0], bz1 = b2[z1];
        float p0 = 0.f, p1 = 0.f;
        #pragma unroll
        for (int j = 0; j < 4; j++) {
            int sa = s0 + wn * 32 + j * 8 + 2 * tq;
            if (sa < len) {
                p0 += fmaxf(zc[j][0] + bz0, 0.f);
                p1 += fmaxf(zc[j][2] + bz1, 0.f);
            }
            if (sa + 1 < len) {
                p0 += fmaxf(zc[j][1] + bz0, 0.f);
                p1 += fmaxf(zc[j][3] + bz1, 0.f);
            }
        }
        p0 += __shfl_xor_sync(0xffffffffu, p0, 1);
        p0 += __shfl_xor_sync(0xffffffffu, p0, 2);
        p1 += __shfl_xor_sync(0xffffffffu, p1, 1);
        p1 += __shfl_xor_sync(0xffffffffu, p1, 2);
        if (tq == 0) {
            red[wq * 16 + gid]     = p0;
            red[wq * 16 + gid + 8] = p1;
        }
    }
    __syncthreads();
    if (tid < ZD) {
        int zq = tid >> 4, zr = tid & 15;   // zq = wm, zr = row within 16
        float s = 0.f;
        #pragma unroll
        for (int wnn = 0; wnn < 4; wnn++)
            s += red[(zq * 4 + wnn) * 16 + zr];
        g_zpart[(b * NTILES + tile) * ZD + tid] = s;
    }
}

// ---------------------------------------------------------------------------
// Tail: z = sum of partials; d = relu(z@W3+b3); y = d@W4 + b4.
// ---------------------------------------------------------------------------
__global__ void tail_kernel(const int* __restrict__ lengths,
                            const float* __restrict__ W3, const float* __restrict__ b3,
                            const float* __restrict__ W4, const float* __restrict__ b4,
                            float* __restrict__ y) {
    __shared__ float z_b[ZD];
    __shared__ float redc[DECH];
    int b = blockIdx.x;
    int tid = threadIdx.x;
    int len = lengths[b];
    int ntiles = (len + TS - 1) / TS;
    if (tid < ZD) {
        float s = 0.f;
        for (int t = 0; t < ntiles; t++) s += g_zpart[(b * NTILES + t) * ZD + tid];
        z_b[tid] = s;
    }
    __syncthreads();
    float acc = b3[tid];
    #pragma unroll 8
    for (int k = 0; k < ZD; k++) acc = fmaf(z_b[k], W3[k * DECH + tid], acc);
    redc[tid] = fmaxf(acc, 0.f) * W4[tid];
    __syncthreads();
    #pragma unroll
    for (int o = DECH / 2; o > 0; o >>= 1) {
        if (tid < o) redc[tid] += redc[tid + o];
        __syncthreads();
    }
    if (tid == 0) y[b] = redc[0] + b4[0];
}

// ---------------------------------------------------------------------------
extern "C" void kernel_launch(void* const* d_in, const int* in_sizes, int n_in,
                              void* d_out, int out_size) {
    const float* u       = (const float*)d_in[0];
    const int*   lengths = (const int*)  d_in[1];
    const float* W1      = (const float*)d_in[2];
    const float* b1      = (const float*)d_in[3];
    const float* W2      = (const float*)d_in[4];
    const float* b2      = (const float*)d_in[5];
    const float* W3      = (const float*)d_in[6];
    const float* b3      = (const float*)d_in[7];
    const float* W4      = (const float*)d_in[8];
    const float* b4      = (const float*)d_in[9];
    float* y = (float*)d_out;

    static int smem_set = 0;
    if (!smem_set) {
        cudaFuncSetAttribute((const void*)main_kernel,
                             cudaFuncAttributeMaxDynamicSharedMemorySize, SMEM_SZ);
        smem_set = 1;
    }

    rowsum_kernel<<<2048, 256>>>(u, lengths);
    cvec_kernel<<<B_, ENCH>>>(W1, b1);
    prep_w1t<<<512, 256>>>(W1);
    prep_w2t<<<128, 256>>>(W2);

    dim3 grid(NTILES, B_);
    main_kernel<<<grid, 512, SMEM_SZ>>>(u, lengths, b2);

    tail_kernel<<<B_, DECH>>>(lengths, W3, b3, W4, b4, y);
}

// round 8
// speedup vs baseline: 4.3850x; 1.0063x over previous
#include <cuda_runtime.h>
#include <cuda_bf16.h>

typedef unsigned int u32;
typedef unsigned long long u64;

#define B_   64
#define NGF  256
#define S_   2048
#define ENCH 512
#define ZD   64
#define DECH 256
#define TS   128
#define NTILES 16

// ---- smem byte offsets ----
#define U_HI   0         // [256 g][128 s] bf16  64KB
#define U_LO   65536
#define A1_HI  131072    // [64 h][256 g] bf16   32KB
#define A1_LO  163840
#define W2_HI  131072    // overlay on A1 (after GEMM1 done): [64 z][64 h] 8KB
#define W2_LO  139264
#define HT_HI  196608    // [64 h][128 s] bf16   16KB
#define HT_LO  212992
#define RED_O  229376    // 256 floats
#define SMEM_SZ 230400

__device__ float g_w[B_*NGF];
__device__ float g_c[B_*ENCH];
__device__ float g_zpart[B_*NTILES*ZD];
__device__ __nv_bfloat16 g_w1t_hi[ENCH*NGF];   // [h][g] = hi(W1[g][h])
__device__ __nv_bfloat16 g_w1t_lo[ENCH*NGF];
__device__ __nv_bfloat16 g_w2t_hi[ZD*ENCH];    // [z][h] = hi(W2[h][z])
__device__ __nv_bfloat16 g_w2t_lo[ZD*ENCH];

// ---- helpers ---------------------------------------------------------------
__device__ __forceinline__ u32 smem_u32(const void* p) {
    u32 a;
    asm("{ .reg .u64 t; cvta.to.shared.u64 t, %1; cvt.u32.u64 %0, t; }"
        : "=r"(a) : "l"(p));
    return a;
}
__device__ __forceinline__ void ldsm4(u32* r, u32 addr) {
    asm volatile("ldmatrix.sync.aligned.m8n8.x4.shared.b16 {%0,%1,%2,%3}, [%4];"
        : "=r"(r[0]), "=r"(r[1]), "=r"(r[2]), "=r"(r[3]) : "r"(addr));
}
__device__ __forceinline__ void ldsm4t(u32* r, u32 addr) {
    asm volatile("ldmatrix.sync.aligned.m8n8.x4.trans.shared.b16 {%0,%1,%2,%3}, [%4];"
        : "=r"(r[0]), "=r"(r[1]), "=r"(r[2]), "=r"(r[3]) : "r"(addr));
}
__device__ __forceinline__ void mma_bf(float* c, const u32* a, u32 b0, u32 b1) {
    asm volatile("mma.sync.aligned.m16n8k16.row.col.f32.bf16.bf16.f32 "
        "{%0,%1,%2,%3}, {%4,%5,%6,%7}, {%8,%9}, {%0,%1,%2,%3};"
        : "+f"(c[0]), "+f"(c[1]), "+f"(c[2]), "+f"(c[3])
        : "r"(a[0]), "r"(a[1]), "r"(a[2]), "r"(a[3]), "r"(b0), "r"(b1));
}
// pack (v0->low, v1->high) hi/lo bf16 splits
__device__ __forceinline__ void split2(float v0, float v1, u32& ph, u32& pl) {
    asm("cvt.rn.bf16x2.f32 %0, %1, %2;" : "=r"(ph) : "f"(v1), "f"(v0));
    float h0 = __uint_as_float(ph << 16);
    float h1 = __uint_as_float(ph & 0xffff0000u);
    float l0 = v0 - h0, l1 = v1 - h1;
    asm("cvt.rn.bf16x2.f32 %0, %1, %2;" : "=r"(pl) : "f"(l1), "f"(l0));
}

// ---------------------------------------------------------------------------
// Prep kernels
// ---------------------------------------------------------------------------
__global__ void rowsum_kernel(const float* __restrict__ u,
                              const int* __restrict__ lengths) {
    int warp = (blockIdx.x * blockDim.x + threadIdx.x) >> 5;
    int lane = threadIdx.x & 31;
    if (warp >= B_ * NGF) return;
    int b = warp >> 8;
    int len = lengths[b];
    const float* row = u + (size_t)warp * S_;
    float sum = 0.f;
    for (int s = lane; s < len; s += 32) sum += row[s];
    #pragma unroll
    for (int o = 16; o > 0; o >>= 1) sum += __shfl_down_sync(0xffffffffu, sum, o);
    if (lane == 0) g_w[warp] = sum;
}

__global__ void cvec_kernel(const float* __restrict__ W1,
                            const float* __restrict__ b1) {
    __shared__ float wsh[NGF];
    int b = blockIdx.x;
    int h = threadIdx.x;          // 512 threads
    if (h < NGF) wsh[h] = g_w[b * NGF + h];
    __syncthreads();
    float acc = b1[h];
    const float* Wp = W1 + (size_t)NGF * ENCH + h;
    #pragma unroll 8
    for (int g = 0; g < NGF; g++) acc = fmaf(wsh[g], Wp[(size_t)g * ENCH], acc);
    g_c[b * ENCH + h] = acc;
}

__global__ void prep_w1t(const float* __restrict__ W1) {
    int idx = blockIdx.x * 256 + threadIdx.x;     // 512*256
    int h = idx >> 8, g = idx & 255;
    float x = W1[(size_t)g * ENCH + h];
    __nv_bfloat16 hi = __float2bfloat16(x);
    g_w1t_hi[h * NGF + g] = hi;
    g_w1t_lo[h * NGF + g] = __float2bfloat16(x - __bfloat162float(hi));
}

__global__ void prep_w2t(const float* __restrict__ W2) {
    int idx = blockIdx.x * 256 + threadIdx.x;     // 64*512
    int z = idx >> 9, h = idx & 511;
    float x = W2[(size_t)h * ZD + z];
    __nv_bfloat16 hi = __float2bfloat16(x);
    g_w2t_hi[z * ENCH + h] = hi;
    g_w2t_lo[z * ENCH + h] = __float2bfloat16(x - __bfloat162float(hi));
}

// ---------------------------------------------------------------------------
// Main HMMA kernel: per (b, 128-s tile). 256 threads = 8 warps (2m x 4n),
// warp tile m32 x n32 (8 accumulator tiles, round-robin MMA issue).
// ---------------------------------------------------------------------------
__global__ void __launch_bounds__(256)
main_kernel(const float* __restrict__ u, const int* __restrict__ lengths,
            const float* __restrict__ b2) {
    extern __shared__ char smem[];
    u32 sb = smem_u32(smem);
    int b = blockIdx.y, tile = blockIdx.x;
    int len = lengths[b];
    int s0 = tile * TS;
    if (s0 >= len) return;

    int tid = threadIdx.x;
    int lane = tid & 31;
    int wq = tid >> 5;         // 0..7
    int wm = wq >> 2;          // 0..1  (m: 32 rows each)
    int wn = wq & 3;           // 0..3  (n: 32 s cols each)
    int gid = lane >> 2, tq = lane & 3;
    int l16 = lane & 15;
    int asel = lane >> 4;

    // ---- load u tile fp32, split -> U_HI/U_LO [g][s] swizzled ----
    const float* ub = u + ((size_t)b * NGF) * S_ + s0;
    #pragma unroll 4
    for (int it = 0; it < 32; it++) {
        int i = tid + 256 * it;
        int g = i >> 5, q = i & 31;
        float4 v = *(const float4*)(ub + (size_t)g * S_ + q * 4);
        u32 ph0, pl0, ph1, pl1;
        split2(v.x, v.y, ph0, pl0);
        split2(v.z, v.w, ph1, pl1);
        u32 off = (u32)(g * 256 + (((q >> 1) ^ (g & 7)) << 4) + ((q & 1) << 3));
        *(uint2*)(smem + U_HI + off) = make_uint2(ph0, ph1);
        *(uint2*)(smem + U_LO + off) = make_uint2(pl0, pl1);
    }
    __syncthreads();

    float zc[2][4][4];
    #pragma unroll
    for (int mt = 0; mt < 2; mt++)
        #pragma unroll
        for (int j = 0; j < 4; j++)
            #pragma unroll
            for (int r = 0; r < 4; r++) zc[mt][j][r] = 0.f;

    const float* cb = g_c + b * ENCH;

    for (int hc = 0; hc < 8; hc++) {
        // ---- load A1 slice (W1T rows hc*64..+63, all 256 g) hi+lo ----
        #pragma unroll
        for (int it = 0; it < 8; it++) {
            int idx = tid + 256 * it;          // 2048 uint4 per plane
            int h = idx >> 5, c = idx & 31;
            u32 off = (u32)(h * 512 + ((c ^ (h & 7)) << 4));
            const __nv_bfloat16* s1 = g_w1t_hi + ((size_t)(hc * 64 + h)) * NGF + c * 8;
            const __nv_bfloat16* s2 = g_w1t_lo + ((size_t)(hc * 64 + h)) * NGF + c * 8;
            *(uint4*)(smem + A1_HI + off) = *(const uint4*)s1;
            *(uint4*)(smem + A1_LO + off) = *(const uint4*)s2;
        }
        __syncthreads();

        float hacc[2][4][4];
        #pragma unroll
        for (int mt = 0; mt < 2; mt++)
            #pragma unroll
            for (int j = 0; j < 4; j++)
                #pragma unroll
                for (int r = 0; r < 4; r++) hacc[mt][j][r] = 0.f;

        // ---- GEMM1: K = 256 (16 k16-steps), m32n32 per warp ----
        #pragma unroll 2
        for (int k = 0; k < 16; k++) {
            u32 ah[2][4], al[2][4], bh[2][4], bl[2][4];
            #pragma unroll
            for (int mt = 0; mt < 2; mt++) {
                int arow = 32 * wm + 16 * mt + l16;
                u32 ach = (u32)(((2 * k + asel) ^ (arow & 7)) << 4);
                ldsm4(ah[mt], sb + A1_HI + arow * 512 + ach);
                ldsm4(al[mt], sb + A1_LO + arow * 512 + ach);
            }
            int brow = 16 * k + l16;
            #pragma unroll
            for (int j = 0; j < 2; j++) {
                u32 bc = (u32)(((4 * wn + 2 * j + asel) ^ (brow & 7)) << 4);
                u32 boff = (u32)(brow * 256) + bc;
                ldsm4t(bh[j], sb + U_HI + boff);
                ldsm4t(bl[j], sb + U_LO + boff);
            }
            // term1: hi*hi   (round-robin over 8 tiles)
            #pragma unroll
            for (int mt = 0; mt < 2; mt++)
                #pragma unroll
                for (int j = 0; j < 2; j++) {
                    mma_bf(hacc[mt][2 * j],     ah[mt], bh[j][0], bh[j][1]);
                    mma_bf(hacc[mt][2 * j + 1], ah[mt], bh[j][2], bh[j][3]);
                }
            // term2: hi*lo
            #pragma unroll
            for (int mt = 0; mt < 2; mt++)
                #pragma unroll
                for (int j = 0; j < 2; j++) {
                    mma_bf(hacc[mt][2 * j],     ah[mt], bl[j][0], bl[j][1]);
                    mma_bf(hacc[mt][2 * j + 1], ah[mt], bl[j][2], bl[j][3]);
                }
            // term3: lo*hi
            #pragma unroll
            for (int mt = 0; mt < 2; mt++)
                #pragma unroll
                for (int j = 0; j < 2; j++) {
                    mma_bf(hacc[mt][2 * j],     al[mt], bh[j][0], bh[j][1]);
                    mma_bf(hacc[mt][2 * j + 1], al[mt], bh[j][2], bh[j][3]);
                }
        }
        __syncthreads();   // all warps done reading A1 before W2 overlay

        // ---- epilogue: bias+relu, split, store H^T [hloc][s] ----
        #pragma unroll
        for (int mt = 0; mt < 2; mt++) {
            int hl0 = 32 * wm + 16 * mt + gid, hl1 = hl0 + 8;
            float bia0 = cb[hc * 64 + hl0], bia1 = cb[hc * 64 + hl1];
            #pragma unroll
            for (int j = 0; j < 4; j++) {
                int sbse = wn * 32 + j * 8;
                float v00 = fmaxf(hacc[mt][j][0] + bia0, 0.f);
                float v01 = fmaxf(hacc[mt][j][1] + bia0, 0.f);
                float v10 = fmaxf(hacc[mt][j][2] + bia1, 0.f);
                float v11 = fmaxf(hacc[mt][j][3] + bia1, 0.f);
                u32 ph, pl;
                split2(v00, v01, ph, pl);
                u32 off0 = (u32)(hl0 * 256 + (((sbse >> 3) ^ (hl0 & 7)) << 4) + 4 * tq);
                *(u32*)(smem + HT_HI + off0) = ph;
                *(u32*)(smem + HT_LO + off0) = pl;
                split2(v10, v11, ph, pl);
                u32 off1 = (u32)(hl1 * 256 + (((sbse >> 3) ^ (hl1 & 7)) << 4) + 4 * tq);
                *(u32*)(smem + HT_HI + off1) = ph;
                *(u32*)(smem + HT_LO + off1) = pl;
            }
        }
        // ---- load W2T slice [64 z][64 h-chunk] hi+lo (overlay) ----
        #pragma unroll
        for (int it = 0; it < 2; it++) {
            int idx = tid + 256 * it;          // 512 uint4 per plane
            int z = idx >> 3, c = idx & 7;
            u32 off = (u32)(z * 128 + ((c ^ (z & 7)) << 4));
            *(uint4*)(smem + W2_HI + off) =
                *(const uint4*)(g_w2t_hi + (size_t)z * ENCH + hc * 64 + c * 8);
            *(uint4*)(smem + W2_LO + off) =
                *(const uint4*)(g_w2t_lo + (size_t)z * ENCH + hc * 64 + c * 8);
        }
        __syncthreads();

        // ---- GEMM2 partial: K = 64 (4 k16-steps), m32n32 per warp ----
        #pragma unroll
        for (int k2 = 0; k2 < 4; k2++) {
            u32 ah[2][4], al[2][4], bh[2][4], bl[2][4];
            #pragma unroll
            for (int mt = 0; mt < 2; mt++) {
                int arow = 32 * wm + 16 * mt + l16;
                u32 ach = (u32)(((2 * k2 + asel) ^ (arow & 7)) << 4);
                ldsm4(ah[mt], sb + W2_HI + arow * 128 + ach);
                ldsm4(al[mt], sb + W2_LO + arow * 128 + ach);
            }
            int brow = 16 * k2 + l16;
            #pragma unroll
            for (int j = 0; j < 2; j++) {
                u32 bc = (u32)(((4 * wn + 2 * j + asel) ^ (brow & 7)) << 4);
                u32 boff = (u32)(brow * 256) + bc;
                ldsm4t(bh[j], sb + HT_HI + boff);
                ldsm4t(bl[j], sb + HT_LO + boff);
            }
            #pragma unroll
            for (int mt = 0; mt < 2; mt++)
                #pragma unroll
                for (int j = 0; j < 2; j++) {
                    mma_bf(zc[mt][2 * j],     ah[mt], bh[j][0], bh[j][1]);
                    mma_bf(zc[mt][2 * j + 1], ah[mt], bh[j][2], bh[j][3]);
                }
            #pragma unroll
            for (int mt = 0; mt < 2; mt++)
                #pragma unroll
                for (int j = 0; j < 2; j++) {
                    mma_bf(zc[mt][2 * j],     ah[mt], bl[j][0], bl[j][1]);
                    mma_bf(zc[mt][2 * j + 1], ah[mt], bl[j][2], bl[j][3]);
                }
            #pragma unroll
            for (int mt = 0; mt < 2; mt++)
                #pragma unroll
                for (int j = 0; j < 2; j++) {
                    mma_bf(zc[mt][2 * j],     al[mt], bh[j][0], bh[j][1]);
                    mma_bf(zc[mt][2 * j + 1], al[mt], bh[j][2], bh[j][3]);
                }
        }
        __syncthreads();   // Ht/W2 consumed; safe to overwrite next chunk
    }

    // ---- final: bias+relu+mask, reduce over s ----
    float* red = (float*)(smem + RED_O);
    #pragma unroll
    for (int mt = 0; mt < 2; mt++) {
        int z0 = 32 * wm + 16 * mt + gid, z1 = z0 + 8;
        float bz0 = b2[z0], bz1 = b2[z1];
        float p0 = 0.f, p1 = 0.f;
        #pragma unroll
        for (int j = 0; j < 4; j++) {
            int sa = s0 + wn * 32 + j * 8 + 2 * tq;
            if (sa < len) {
                p0 += fmaxf(zc[mt][j][0] + bz0, 0.f);
                p1 += fmaxf(zc[mt][j][2] + bz1, 0.f);
            }
            if (sa + 1 < len) {
                p0 += fmaxf(zc[mt][j][1] + bz0, 0.f);
                p1 += fmaxf(zc[mt][j][3] + bz1, 0.f);
            }
        }
        p0 += __shfl_xor_sync(0xffffffffu, p0, 1);
        p0 += __shfl_xor_sync(0xffffffffu, p0, 2);
        p1 += __shfl_xor_sync(0xffffffffu, p1, 1);
        p1 += __shfl_xor_sync(0xffffffffu, p1, 2);
        if (tq == 0) {
            red[wn * 64 + z0] = p0;
            red[wn * 64 + z1] = p1;
        }
    }
    __syncthreads();
    if (tid < ZD) {
        float s = 0.f;
        #pragma unroll
        for (int wnn = 0; wnn < 4; wnn++) s += red[wnn * 64 + tid];
        g_zpart[(b * NTILES + tile) * ZD + tid] = s;
    }
}

// ---------------------------------------------------------------------------
// Tail: z = sum of partials; d = relu(z@W3+b3); y = d@W4 + b4.
// ---------------------------------------------------------------------------
__global__ void tail_kernel(const int* __restrict__ lengths,
                            const float* __restrict__ W3, const float* __restrict__ b3,
                            const float* __restrict__ W4, const float* __restrict__ b4,
                            float* __restrict__ y) {
    __shared__ float z_b[ZD];
    __shared__ float redc[DECH];
    int b = blockIdx.x;
    int tid = threadIdx.x;
    int len = lengths[b];
    int ntiles = (len + TS - 1) / TS;
    if (tid < ZD) {
        float s = 0.f;
        for (int t = 0; t < ntiles; t++) s += g_zpart[(b * NTILES + t) * ZD + tid];
        z_b[tid] = s;
    }
    __syncthreads();
    float acc = b3[tid];
    #pragma unroll 8
    for (int k = 0; k < ZD; k++) acc = fmaf(z_b[k], W3[k * DECH + tid], acc);
    redc[tid] = fmaxf(acc, 0.f) * W4[tid];
    __syncthreads();
    #pragma unroll
    for (int o = DECH / 2; o > 0; o >>= 1) {
        if (tid < o) redc[tid] += redc[tid + o];
        __syncthreads();
    }
    if (tid == 0) y[b] = redc[0] + b4[0];
}

// ---------------------------------------------------------------------------
extern "C" void kernel_launch(void* const* d_in, const int* in_sizes, int n_in,
                              void* d_out, int out_size) {
    const float* u       = (const float*)d_in[0];
    const int*   lengths = (const int*)  d_in[1];
    const float* W1      = (const float*)d_in[2];
    const float* b1      = (const float*)d_in[3];
    const float* W2      = (const float*)d_in[4];
    const float* b2      = (const float*)d_in[5];
    const float* W3      = (const float*)d_in[6];
    const float* b3      = (const float*)d_in[7];
    const float* W4      = (const float*)d_in[8];
    const float* b4      = (const float*)d_in[9];
    float* y = (float*)d_out;

    static int smem_set = 0;
    if (!smem_set) {
        cudaFuncSetAttribute((const void*)main_kernel,
                             cudaFuncAttributeMaxDynamicSharedMemorySize, SMEM_SZ);
        smem_set = 1;
    }

    rowsum_kernel<<<2048, 256>>>(u, lengths);
    cvec_kernel<<<B_, ENCH>>>(W1, b1);
    prep_w1t<<<512, 256>>>(W1);
    prep_w2t<<<128, 256>>>(W2);

    dim3 grid(NTILES, B_);
    main_kernel<<<grid, 256, SMEM_SZ>>>(u, lengths, b2);

    tail_kernel<<<B_, DECH>>>(lengths, W3, b3, W4, b4, y);
}

// round 10
// speedup vs baseline: 5.7413x; 1.3093x over previous
#include <cuda_runtime.h>
#include <cuda_fp16.h>

typedef unsigned int u32;
typedef unsigned long long u64;

#define B_   64
#define NGF  256
#define S_   2048
#define ENCH 512
#define ZD   64
#define DECH 256
#define TS   128
#define NTILES 16

// ---- smem byte offsets ----
#define U_HI   0         // [256 g][128 s] fp16  64KB (single limb)
#define A1_HI  65536     // [64 h][256 g] fp16   32KB
#define A1_LO  98304
#define W2_HI  65536     // overlay on A1 (after GEMM1 done): [64 z][64 h] 8KB
#define W2_LO  73728
#define HT_HI  131072    // [64 h][128 s] fp16   16KB (single limb)
#define RED_O  147456    // 256 floats
#define SMEM_SZ 148480

__device__ float g_w[B_*NGF];
__device__ float g_c[B_*ENCH];
__device__ float g_zpart[B_*NTILES*ZD];
__device__ __half g_w1t_hi[ENCH*NGF];   // [h][g] = hi(W1[g][h])
__device__ __half g_w1t_lo[ENCH*NGF];
__device__ __half g_w2t_hi[ZD*ENCH];    // [z][h] = hi(W2[h][z])
__device__ __half g_w2t_lo[ZD*ENCH];

// ---- helpers ---------------------------------------------------------------
__device__ __forceinline__ u32 smem_u32(const void* p) {
    u32 a;
    asm("{ .reg .u64 t; cvta.to.shared.u64 t, %1; cvt.u32.u64 %0, t; }"
        : "=r"(a) : "l"(p));
    return a;
}
__device__ __forceinline__ void ldsm4(u32* r, u32 addr) {
    asm volatile("ldmatrix.sync.aligned.m8n8.x4.shared.b16 {%0,%1,%2,%3}, [%4];"
        : "=r"(r[0]), "=r"(r[1]), "=r"(r[2]), "=r"(r[3]) : "r"(addr));
}
__device__ __forceinline__ void ldsm4t(u32* r, u32 addr) {
    asm volatile("ldmatrix.sync.aligned.m8n8.x4.trans.shared.b16 {%0,%1,%2,%3}, [%4];"
        : "=r"(r[0]), "=r"(r[1]), "=r"(r[2]), "=r"(r[3]) : "r"(addr));
}
__device__ __forceinline__ void mma_h(float* c, const u32* a, u32 b0, u32 b1) {
    asm volatile("mma.sync.aligned.m16n8k16.row.col.f32.f16.f16.f32 "
        "{%0,%1,%2,%3}, {%4,%5,%6,%7}, {%8,%9}, {%0,%1,%2,%3};"
        : "+f"(c[0]), "+f"(c[1]), "+f"(c[2]), "+f"(c[3])
        : "r"(a[0]), "r"(a[1]), "r"(a[2]), "r"(a[3]), "r"(b0), "r"(b1));
}
__device__ __forceinline__ u32 packh2(float lo, float hi) {
    __half2 h = __floats2half2_rn(lo, hi);
    return *(u32*)&h;
}

// ---------------------------------------------------------------------------
// Prep kernels
// ---------------------------------------------------------------------------
__global__ void rowsum_kernel(const float* __restrict__ u,
                              const int* __restrict__ lengths) {
    int warp = (blockIdx.x * blockDim.x + threadIdx.x) >> 5;
    int lane = threadIdx.x & 31;
    if (warp >= B_ * NGF) return;
    int b = warp >> 8;
    int len = lengths[b];
    const float* row = u + (size_t)warp * S_;
    float sum = 0.f;
    for (int s = lane; s < len; s += 32) sum += row[s];
    #pragma unroll
    for (int o = 16; o > 0; o >>= 1) sum += __shfl_down_sync(0xffffffffu, sum, o);
    if (lane == 0) g_w[warp] = sum;
}

__global__ void cvec_kernel(const float* __restrict__ W1,
                            const float* __restrict__ b1) {
    __shared__ float wsh[NGF];
    int b = blockIdx.x;
    int h = threadIdx.x;          // 512 threads
    if (h < NGF) wsh[h] = g_w[b * NGF + h];
    __syncthreads();
    float acc = b1[h];
    const float* Wp = W1 + (size_t)NGF * ENCH + h;
    #pragma unroll 8
    for (int g = 0; g < NGF; g++) acc = fmaf(wsh[g], Wp[(size_t)g * ENCH], acc);
    g_c[b * ENCH + h] = acc;
}

__global__ void prep_w1t(const float* __restrict__ W1) {
    int idx = blockIdx.x * 256 + threadIdx.x;     // 512*256
    int h = idx >> 8, g = idx & 255;
    float x = W1[(size_t)g * ENCH + h];
    __half hi = __float2half_rn(x);
    g_w1t_hi[h * NGF + g] = hi;
    g_w1t_lo[h * NGF + g] = __float2half_rn(x - __half2float(hi));
}

__global__ void prep_w2t(const float* __restrict__ W2) {
    int idx = blockIdx.x * 256 + threadIdx.x;     // 64*512
    int z = idx >> 9, h = idx & 511;
    float x = W2[(size_t)h * ZD + z];
    __half hi = __float2half_rn(x);
    g_w2t_hi[z * ENCH + h] = hi;
    g_w2t_lo[z * ENCH + h] = __float2half_rn(x - __half2float(hi));
}

// ---------------------------------------------------------------------------
// Main HMMA kernel: per (b, 128-s tile). 256 threads = 8 warps (2m x 4n),
// warp tile m32 x n32. 2-term fp16 split: weights hi+lo, activations single.
// ---------------------------------------------------------------------------
__global__ void __launch_bounds__(256)
main_kernel(const float* __restrict__ u, const int* __restrict__ lengths,
            const float* __restrict__ b2) {
    extern __shared__ char smem[];
    u32 sb = smem_u32(smem);
    int b = blockIdx.y, tile = blockIdx.x;
    int len = lengths[b];
    int s0 = tile * TS;
    if (s0 >= len) return;

    int tid = threadIdx.x;
    int lane = tid & 31;
    int wq = tid >> 5;         // 0..7
    int wm = wq >> 2;          // 0..1  (m: 32 rows each)
    int wn = wq & 3;           // 0..3  (n: 32 s cols each)
    int gid = lane >> 2, tq = lane & 3;
    int l16 = lane & 15;
    int asel = lane >> 4;

    // ---- load u tile fp32 -> single fp16, [g][s] swizzled ----
    const float* ub = u + ((size_t)b * NGF) * S_ + s0;
    #pragma unroll 4
    for (int it = 0; it < 32; it++) {
        int i = tid + 256 * it;
        int g = i >> 5, q = i & 31;
        float4 v = *(const float4*)(ub + (size_t)g * S_ + q * 4);
        u32 off = (u32)(g * 256 + (((q >> 1) ^ (g & 7)) << 4) + ((q & 1) << 3));
        *(uint2*)(smem + U_HI + off) = make_uint2(packh2(v.x, v.y), packh2(v.z, v.w));
    }
    __syncthreads();

    float zc[2][4][4];
    #pragma unroll
    for (int mt = 0; mt < 2; mt++)
        #pragma unroll
        for (int j = 0; j < 4; j++)
            #pragma unroll
            for (int r = 0; r < 4; r++) zc[mt][j][r] = 0.f;

    const float* cb = g_c + b * ENCH;

    for (int hc = 0; hc < 8; hc++) {
        // ---- load A1 slice (W1T rows hc*64..+63, all 256 g) hi+lo ----
        #pragma unroll
        for (int it = 0; it < 8; it++) {
            int idx = tid + 256 * it;          // 2048 uint4 per plane
            int h = idx >> 5, c = idx & 31;
            u32 off = (u32)(h * 512 + ((c ^ (h & 7)) << 4));
            const __half* s1 = g_w1t_hi + ((size_t)(hc * 64 + h)) * NGF + c * 8;
            const __half* s2 = g_w1t_lo + ((size_t)(hc * 64 + h)) * NGF + c * 8;
            *(uint4*)(smem + A1_HI + off) = *(const uint4*)s1;
            *(uint4*)(smem + A1_LO + off) = *(const uint4*)s2;
        }
        __syncthreads();

        float hacc[2][4][4];
        #pragma unroll
        for (int mt = 0; mt < 2; mt++)
            #pragma unroll
            for (int j = 0; j < 4; j++)
                #pragma unroll
                for (int r = 0; r < 4; r++) hacc[mt][j][r] = 0.f;

        // ---- GEMM1: K = 256 (16 k16-steps), m32n32 per warp, 16 MMA/step ----
        #pragma unroll 2
        for (int k = 0; k < 16; k++) {
            u32 ah[2][4], al[2][4], bh[2][4];
            #pragma unroll
            for (int mt = 0; mt < 2; mt++) {
                int arow = 32 * wm + 16 * mt + l16;
                u32 ach = (u32)(((2 * k + asel) ^ (arow & 7)) << 4);
                ldsm4(ah[mt], sb + A1_HI + arow * 512 + ach);
                ldsm4(al[mt], sb + A1_LO + arow * 512 + ach);
            }
            int brow = 16 * k + l16;
            #pragma unroll
            for (int j = 0; j < 2; j++) {
                u32 bc = (u32)(((4 * wn + 2 * j + asel) ^ (brow & 7)) << 4);
                ldsm4t(bh[j], sb + U_HI + (u32)(brow * 256) + bc);
            }
            // term1: hi(W)*u
            #pragma unroll
            for (int mt = 0; mt < 2; mt++)
                #pragma unroll
                for (int j = 0; j < 2; j++) {
                    mma_h(hacc[mt][2 * j],     ah[mt], bh[j][0], bh[j][1]);
                    mma_h(hacc[mt][2 * j + 1], ah[mt], bh[j][2], bh[j][3]);
                }
            // term2: lo(W)*u
            #pragma unroll
            for (int mt = 0; mt < 2; mt++)
                #pragma unroll
                for (int j = 0; j < 2; j++) {
                    mma_h(hacc[mt][2 * j],     al[mt], bh[j][0], bh[j][1]);
                    mma_h(hacc[mt][2 * j + 1], al[mt], bh[j][2], bh[j][3]);
                }
        }
        __syncthreads();   // all warps done reading A1 before W2 overlay

        // ---- epilogue: bias+relu, single fp16, store H^T [hloc][s] ----
        #pragma unroll
        for (int mt = 0; mt < 2; mt++) {
            int hl0 = 32 * wm + 16 * mt + gid, hl1 = hl0 + 8;
            float bia0 = cb[hc * 64 + hl0], bia1 = cb[hc * 64 + hl1];
            #pragma unroll
            for (int j = 0; j < 4; j++) {
                int sbse = wn * 32 + j * 8;
                float v00 = fmaxf(hacc[mt][j][0] + bia0, 0.f);
                float v01 = fmaxf(hacc[mt][j][1] + bia0, 0.f);
                float v10 = fmaxf(hacc[mt][j][2] + bia1, 0.f);
                float v11 = fmaxf(hacc[mt][j][3] + bia1, 0.f);
                u32 off0 = (u32)(hl0 * 256 + (((sbse >> 3) ^ (hl0 & 7)) << 4) + 4 * tq);
                *(u32*)(smem + HT_HI + off0) = packh2(v00, v01);
                u32 off1 = (u32)(hl1 * 256 + (((sbse >> 3) ^ (hl1 & 7)) << 4) + 4 * tq);
                *(u32*)(smem + HT_HI + off1) = packh2(v10, v11);
            }
        }
        // ---- load W2T slice [64 z][64 h-chunk] hi+lo (overlay) ----
        #pragma unroll
        for (int it = 0; it < 2; it++) {
            int idx = tid + 256 * it;          // 512 uint4 per plane
            int z = idx >> 3, c = idx & 7;
            u32 off = (u32)(z * 128 + ((c ^ (z & 7)) << 4));
            *(uint4*)(smem + W2_HI + off) =
                *(const uint4*)(g_w2t_hi + (size_t)z * ENCH + hc * 64 + c * 8);
            *(uint4*)(smem + W2_LO + off) =
                *(const uint4*)(g_w2t_lo + (size_t)z * ENCH + hc * 64 + c * 8);
        }
        __syncthreads();

        // ---- GEMM2 partial: K = 64 (4 k16-steps), 16 MMA/step ----
        #pragma unroll
        for (int k2 = 0; k2 < 4; k2++) {
            u32 ah[2][4], al[2][4], bh[2][4];
            #pragma unroll
            for (int mt = 0; mt < 2; mt++) {
                int arow = 32 * wm + 16 * mt + l16;
                u32 ach = (u32)(((2 * k2 + asel) ^ (arow & 7)) << 4);
                ldsm4(ah[mt], sb + W2_HI + arow * 128 + ach);
                ldsm4(al[mt], sb + W2_LO + arow * 128 + ach);
            }
            int brow = 16 * k2 + l16;
            #pragma unroll
            for (int j = 0; j < 2; j++) {
                u32 bc = (u32)(((4 * wn + 2 * j + asel) ^ (brow & 7)) << 4);
                ldsm4t(bh[j], sb + HT_HI + (u32)(brow * 256) + bc);
            }
            #pragma unroll
            for (int mt = 0; mt < 2; mt++)
                #pragma unroll
                for (int j = 0; j < 2; j++) {
                    mma_h(zc[mt][2 * j],     ah[mt], bh[j][0], bh[j][1]);
                    mma_h(zc[mt][2 * j + 1], ah[mt], bh[j][2], bh[j][3]);
                }
            #pragma unroll
            for (int mt = 0; mt < 2; mt++)
                #pragma unroll
                for (int j = 0; j < 2; j++) {
                    mma_h(zc[mt][2 * j],     al[mt], bh[j][0], bh[j][1]);
                    mma_h(zc[mt][2 * j + 1], al[mt], bh[j][2], bh[j][3]);
                }
        }
        __syncthreads();   // Ht/W2 consumed; safe to overwrite next chunk
    }

    // ---- final: bias+relu+mask, reduce over s ----
    float* red = (float*)(smem + RED_O);
    #pragma unroll
    for (int mt = 0; mt < 2; mt++) {
        int z0 = 32 * wm + 16 * mt + gid, z1 = z0 + 8;
        float bz0 = b2[z0], bz1 = b2[z1];
        float p0 = 0.f, p1 = 0.f;
        #pragma unroll
        for (int j = 0; j < 4; j++) {
            int sa = s0 + wn * 32 + j * 8 + 2 * tq;
            if (sa < len) {
                p0 += fmaxf(zc[mt][j][0] + bz0, 0.f);
                p1 += fmaxf(zc[mt][j][2] + bz1, 0.f);
            }
            if (sa + 1 < len) {
                p0 += fmaxf(zc[mt][j][1] + bz0, 0.f);
                p1 += fmaxf(zc[mt][j][3] + bz1, 0.f);
            }
        }
        p0 += __shfl_xor_sync(0xffffffffu, p0, 1);
        p0 += __shfl_xor_sync(0xffffffffu, p0, 2);
        p1 += __shfl_xor_sync(0xffffffffu, p1, 1);
        p1 += __shfl_xor_sync(0xffffffffu, p1, 2);
        if (tq == 0) {
            red[wn * 64 + z0] = p0;
            red[wn * 64 + z1] = p1;
        }
    }
    __syncthreads();
    if (tid < ZD) {
        float s = 0.f;
        #pragma unroll
        for (int wnn = 0; wnn < 4; wnn++) s += red[wnn * 64 + tid];
        g_zpart[(b * NTILES + tile) * ZD + tid] = s;
    }
}

// ---------------------------------------------------------------------------
// Tail: z = sum of partials; d = relu(z@W3+b3); y = d@W4 + b4.
// ---------------------------------------------------------------------------
__global__ void tail_kernel(const int* __restrict__ lengths,
                            const float* __restrict__ W3, const float* __restrict__ b3,
                            const float* __restrict__ W4, const float* __restrict__ b4,
                            float* __restrict__ y) {
    __shared__ float z_b[ZD];
    __shared__ float redc[DECH];
    int b = blockIdx.x;
    int tid = threadIdx.x;
    int len = lengths[b];
    int ntiles = (len + TS - 1) / TS;
    if (tid < ZD) {
        float s = 0.f;
        for (int t = 0; t < ntiles; t++) s += g_zpart[(b * NTILES + t) * ZD + tid];
        z_b[tid] = s;
    }
    __syncthreads();
    float acc = b3[tid];
    #pragma unroll 8
    for (int k = 0; k < ZD; k++) acc = fmaf(z_b[k], W3[k * DECH + tid], acc);
    redc[tid] = fmaxf(acc, 0.f) * W4[tid];
    __syncthreads();
    #pragma unroll
    for (int o = DECH / 2; o > 0; o >>= 1) {
        if (tid < o) redc[tid] += redc[tid + o];
        __syncthreads();
    }
    if (tid == 0) y[b] = redc[0] + b4[0];
}

// ---------------------------------------------------------------------------
extern "C" void kernel_launch(void* const* d_in, const int* in_sizes, int n_in,
                              void* d_out, int out_size) {
    const float* u       = (const float*)d_in[0];
    const int*   lengths = (const int*)  d_in[1];
    const float* W1      = (const float*)d_in[2];
    const float* b1      = (const float*)d_in[3];
    const float* W2      = (const float*)d_in[4];
    const float* b2      = (const float*)d_in[5];
    const float* W3      = (const float*)d_in[6];
    const float* b3      = (const float*)d_in[7];
    const float* W4      = (const float*)d_in[8];
    const float* b4      = (const float*)d_in[9];
    float* y = (float*)d_out;

    static int smem_set = 0;
    if (!smem_set) {
        cudaFuncSetAttribute((const void*)main_kernel,
                             cudaFuncAttributeMaxDynamicSharedMemorySize, SMEM_SZ);
        smem_set = 1;
    }

    rowsum_kernel<<<2048, 256>>>(u, lengths);
    cvec_kernel<<<B_, ENCH>>>(W1, b1);
    prep_w1t<<<512, 256>>>(W1);
    prep_w2t<<<128, 256>>>(W2);

    dim3 grid(NTILES, B_);
    main_kernel<<<grid, 256, SMEM_SZ>>>(u, lengths, b2);

    tail_kernel<<<B_, DECH>>>(lengths, W3, b3, W4, b4, y);
}

// round 11
// speedup vs baseline: 9.0679x; 1.5794x over previous
#include <cuda_runtime.h>
#include <cuda_fp16.h>

typedef unsigned int u32;
typedef unsigned long long u64;

#define B_   64
#define NGF  256
#define S_   2048
#define ENCH 512
#define ZD   64
#define DECH 256
#define TS   128
#define NTILES 16

// ---- smem byte offsets ----
#define U_HI   0         // [256 g][128 s] fp16  64KB
#define A1_HI  65536     // [64 h][256 g] fp16   32KB
#define W2_HI  65536     // overlay on A1 (after GEMM1 done): [64 z][64 h] 8KB
#define HT_HI  98304     // [64 h][128 s] fp16   16KB
#define RED_O  114688    // 256 floats
#define SMEM_SZ 115712

__device__ float g_w[B_*NGF];
__device__ float g_c[B_*ENCH];
__device__ float g_zpart[B_*NTILES*ZD];
__device__ __half g_w1t[ENCH*NGF];   // [h][g] = fp16(W1[g][h])
__device__ __half g_w2t[ZD*ENCH];    // [z][h] = fp16(W2[h][z])

// ---- helpers ---------------------------------------------------------------
__device__ __forceinline__ u32 smem_u32(const void* p) {
    u32 a;
    asm("{ .reg .u64 t; cvta.to.shared.u64 t, %1; cvt.u32.u64 %0, t; }"
        : "=r"(a) : "l"(p));
    return a;
}
__device__ __forceinline__ void ldsm4(u32* r, u32 addr) {
    asm volatile("ldmatrix.sync.aligned.m8n8.x4.shared.b16 {%0,%1,%2,%3}, [%4];"
        : "=r"(r[0]), "=r"(r[1]), "=r"(r[2]), "=r"(r[3]) : "r"(addr));
}
__device__ __forceinline__ void ldsm4t(u32* r, u32 addr) {
    asm volatile("ldmatrix.sync.aligned.m8n8.x4.trans.shared.b16 {%0,%1,%2,%3}, [%4];"
        : "=r"(r[0]), "=r"(r[1]), "=r"(r[2]), "=r"(r[3]) : "r"(addr));
}
__device__ __forceinline__ void mma_h(float* c, const u32* a, u32 b0, u32 b1) {
    asm volatile("mma.sync.aligned.m16n8k16.row.col.f32.f16.f16.f32 "
        "{%0,%1,%2,%3}, {%4,%5,%6,%7}, {%8,%9}, {%0,%1,%2,%3};"
        : "+f"(c[0]), "+f"(c[1]), "+f"(c[2]), "+f"(c[3])
        : "r"(a[0]), "r"(a[1]), "r"(a[2]), "r"(a[3]), "r"(b0), "r"(b1));
}
__device__ __forceinline__ u32 packh2(float lo, float hi) {
    __half2 h = __floats2half2_rn(lo, hi);
    return *(u32*)&h;
}

// ---------------------------------------------------------------------------
// Prep kernels
// ---------------------------------------------------------------------------
__global__ void rowsum_kernel(const float* __restrict__ u,
                              const int* __restrict__ lengths) {
    int warp = (blockIdx.x * blockDim.x + threadIdx.x) >> 5;
    int lane = threadIdx.x & 31;
    if (warp >= B_ * NGF) return;
    int b = warp >> 8;
    int len = lengths[b];
    const float* row = u + (size_t)warp * S_;
    float sum = 0.f;
    for (int s = lane; s < len; s += 32) sum += row[s];
    #pragma unroll
    for (int o = 16; o > 0; o >>= 1) sum += __shfl_down_sync(0xffffffffu, sum, o);
    if (lane == 0) g_w[warp] = sum;
}

__global__ void cvec_kernel(const float* __restrict__ W1,
                            const float* __restrict__ b1) {
    __shared__ float wsh[NGF];
    int b = blockIdx.x;
    int h = threadIdx.x;          // 512 threads
    if (h < NGF) wsh[h] = g_w[b * NGF + h];
    __syncthreads();
    float acc = b1[h];
    const float* Wp = W1 + (size_t)NGF * ENCH + h;
    #pragma unroll 8
    for (int g = 0; g < NGF; g++) acc = fmaf(wsh[g], Wp[(size_t)g * ENCH], acc);
    g_c[b * ENCH + h] = acc;
}

__global__ void prep_w1t(const float* __restrict__ W1) {
    int idx = blockIdx.x * 256 + threadIdx.x;     // 512*256
    int h = idx >> 8, g = idx & 255;
    g_w1t[h * NGF + g] = __float2half_rn(W1[(size_t)g * ENCH + h]);
}

__global__ void prep_w2t(const float* __restrict__ W2) {
    int idx = blockIdx.x * 256 + threadIdx.x;     // 64*512
    int z = idx >> 9, h = idx & 511;
    g_w2t[z * ENCH + h] = __float2half_rn(W2[(size_t)h * ZD + z]);
}

// ---------------------------------------------------------------------------
// Main HMMA kernel: per (b, 128-s tile). 256 threads = 8 warps (2m x 4n),
// warp tile m32 x n32. Pure fp16 operands, fp32 accumulate.
// 113KB smem -> 2 CTAs/SM.
// ---------------------------------------------------------------------------
__global__ void __launch_bounds__(256, 2)
main_kernel(const float* __restrict__ u, const int* __restrict__ lengths,
            const float* __restrict__ b2) {
    extern __shared__ char smem[];
    u32 sb = smem_u32(smem);
    int b = blockIdx.y, tile = blockIdx.x;
    int len = lengths[b];
    int s0 = tile * TS;
    if (s0 >= len) return;

    int tid = threadIdx.x;
    int lane = tid & 31;
    int wq = tid >> 5;         // 0..7
    int wm = wq >> 2;          // 0..1  (m: 32 rows each)
    int wn = wq & 3;           // 0..3  (n: 32 s cols each)
    int gid = lane >> 2, tq = lane & 3;
    int l16 = lane & 15;
    int asel = lane >> 4;

    // ---- load u tile fp32 -> fp16, [g][s] swizzled ----
    const float* ub = u + ((size_t)b * NGF) * S_ + s0;
    #pragma unroll 4
    for (int it = 0; it < 32; it++) {
        int i = tid + 256 * it;
        int g = i >> 5, q = i & 31;
        float4 v = *(const float4*)(ub + (size_t)g * S_ + q * 4);
        u32 off = (u32)(g * 256 + (((q >> 1) ^ (g & 7)) << 4) + ((q & 1) << 3));
        *(uint2*)(smem + U_HI + off) = make_uint2(packh2(v.x, v.y), packh2(v.z, v.w));
    }
    __syncthreads();

    float zc[2][4][4];
    #pragma unroll
    for (int mt = 0; mt < 2; mt++)
        #pragma unroll
        for (int j = 0; j < 4; j++)
            #pragma unroll
            for (int r = 0; r < 4; r++) zc[mt][j][r] = 0.f;

    const float* cb = g_c + b * ENCH;

    for (int hc = 0; hc < 8; hc++) {
        // ---- load A1 slice (W1T rows hc*64..+63, all 256 g) ----
        #pragma unroll
        for (int it = 0; it < 8; it++) {
            int idx = tid + 256 * it;          // 2048 uint4
            int h = idx >> 5, c = idx & 31;
            u32 off = (u32)(h * 512 + ((c ^ (h & 7)) << 4));
            *(uint4*)(smem + A1_HI + off) =
                *(const uint4*)(g_w1t + ((size_t)(hc * 64 + h)) * NGF + c * 8);
        }
        __syncthreads();

        float hacc[2][4][4];
        #pragma unroll
        for (int mt = 0; mt < 2; mt++)
            #pragma unroll
            for (int j = 0; j < 4; j++)
                #pragma unroll
                for (int r = 0; r < 4; r++) hacc[mt][j][r] = 0.f;

        // ---- GEMM1: K = 256 (16 k16-steps), m32n32 per warp, 8 MMA/step ----
        #pragma unroll 4
        for (int k = 0; k < 16; k++) {
            u32 ah[2][4], bh[2][4];
            #pragma unroll
            for (int mt = 0; mt < 2; mt++) {
                int arow = 32 * wm + 16 * mt + l16;
                u32 ach = (u32)(((2 * k + asel) ^ (arow & 7)) << 4);
                ldsm4(ah[mt], sb + A1_HI + arow * 512 + ach);
            }
            int brow = 16 * k + l16;
            #pragma unroll
            for (int j = 0; j < 2; j++) {
                u32 bc = (u32)(((4 * wn + 2 * j + asel) ^ (brow & 7)) << 4);
                ldsm4t(bh[j], sb + U_HI + (u32)(brow * 256) + bc);
            }
            #pragma unroll
            for (int mt = 0; mt < 2; mt++)
                #pragma unroll
                for (int j = 0; j < 2; j++) {
                    mma_h(hacc[mt][2 * j],     ah[mt], bh[j][0], bh[j][1]);
                    mma_h(hacc[mt][2 * j + 1], ah[mt], bh[j][2], bh[j][3]);
                }
        }
        __syncthreads();   // all warps done reading A1 before W2 overlay

        // ---- epilogue: bias+relu, fp16, store H^T [hloc][s] ----
        #pragma unroll
        for (int mt = 0; mt < 2; mt++) {
            int hl0 = 32 * wm + 16 * mt + gid, hl1 = hl0 + 8;
            float bia0 = cb[hc * 64 + hl0], bia1 = cb[hc * 64 + hl1];
            #pragma unroll
            for (int j = 0; j < 4; j++) {
                int sbse = wn * 32 + j * 8;
                float v00 = fmaxf(hacc[mt][j][0] + bia0, 0.f);
                float v01 = fmaxf(hacc[mt][j][1] + bia0, 0.f);
                float v10 = fmaxf(hacc[mt][j][2] + bia1, 0.f);
                float v11 = fmaxf(hacc[mt][j][3] + bia1, 0.f);
                u32 off0 = (u32)(hl0 * 256 + (((sbse >> 3) ^ (hl0 & 7)) << 4) + 4 * tq);
                *(u32*)(smem + HT_HI + off0) = packh2(v00, v01);
                u32 off1 = (u32)(hl1 * 256 + (((sbse >> 3) ^ (hl1 & 7)) << 4) + 4 * tq);
                *(u32*)(smem + HT_HI + off1) = packh2(v10, v11);
            }
        }
        // ---- load W2T slice [64 z][64 h-chunk] (overlay) ----
        {
            int z = tid >> 2, c = tid & 3;     // 64 x 4 of uint4... 256 thr covers 8KB/16B=512? no
        }
        #pragma unroll
        for (int it = 0; it < 2; it++) {
            int idx = tid + 256 * it;          // 512 uint4
            int z = idx >> 3, c = idx & 7;
            u32 off = (u32)(z * 128 + ((c ^ (z & 7)) << 4));
            *(uint4*)(smem + W2_HI + off) =
                *(const uint4*)(g_w2t + (size_t)z * ENCH + hc * 64 + c * 8);
        }
        __syncthreads();

        // ---- GEMM2 partial: K = 64 (4 k16-steps), 8 MMA/step ----
        #pragma unroll
        for (int k2 = 0; k2 < 4; k2++) {
            u32 ah[2][4], bh[2][4];
            #pragma unroll
            for (int mt = 0; mt < 2; mt++) {
                int arow = 32 * wm + 16 * mt + l16;
                u32 ach = (u32)(((2 * k2 + asel) ^ (arow & 7)) << 4);
                ldsm4(ah[mt], sb + W2_HI + arow * 128 + ach);
            }
            int brow = 16 * k2 + l16;
            #pragma unroll
            for (int j = 0; j < 2; j++) {
                u32 bc = (u32)(((4 * wn + 2 * j + asel) ^ (brow & 7)) << 4);
                ldsm4t(bh[j], sb + HT_HI + (u32)(brow * 256) + bc);
            }
            #pragma unroll
            for (int mt = 0; mt < 2; mt++)
                #pragma unroll
                for (int j = 0; j < 2; j++) {
                    mma_h(zc[mt][2 * j],     ah[mt], bh[j][0], bh[j][1]);
                    mma_h(zc[mt][2 * j + 1], ah[mt], bh[j][2], bh[j][3]);
                }
        }
        __syncthreads();   // Ht/W2 consumed; safe to overwrite next chunk
    }

    // ---- final: bias+relu+mask, reduce over s ----
    float* red = (float*)(smem + RED_O);
    #pragma unroll
    for (int mt = 0; mt < 2; mt++) {
        int z0 = 32 * wm + 16 * mt + gid, z1 = z0 + 8;
        float bz0 = b2[z0], bz1 = b2[z1];
        float p0 = 0.f, p1 = 0.f;
        #pragma unroll
        for (int j = 0; j < 4; j++) {
            int sa = s0 + wn * 32 + j * 8 + 2 * tq;
            if (sa < len) {
                p0 += fmaxf(zc[mt][j][0] + bz0, 0.f);
                p1 += fmaxf(zc[mt][j][2] + bz1, 0.f);
            }
            if (sa + 1 < len) {
                p0 += fmaxf(zc[mt][j][1] + bz0, 0.f);
                p1 += fmaxf(zc[mt][j][3] + bz1, 0.f);
            }
        }
        p0 += __shfl_xor_sync(0xffffffffu, p0, 1);
        p0 += __shfl_xor_sync(0xffffffffu, p0, 2);
        p1 += __shfl_xor_sync(0xffffffffu, p1, 1);
        p1 += __shfl_xor_sync(0xffffffffu, p1, 2);
        if (tq == 0) {
            red[wn * 64 + z0] = p0;
            red[wn * 64 + z1] = p1;
        }
    }
    __syncthreads();
    if (tid < ZD) {
        float s = 0.f;
        #pragma unroll
        for (int wnn = 0; wnn < 4; wnn++) s += red[wnn * 64 + tid];
        g_zpart[(b * NTILES + tile) * ZD + tid] = s;
    }
}

// ---------------------------------------------------------------------------
// Tail: z = sum of partials; d = relu(z@W3+b3); y = d@W4 + b4.
// ---------------------------------------------------------------------------
__global__ void tail_kernel(const int* __restrict__ lengths,
                            const float* __restrict__ W3, const float* __restrict__ b3,
                            const float* __restrict__ W4, const float* __restrict__ b4,
                            float* __restrict__ y) {
    __shared__ float z_b[ZD];
    __shared__ float redc[DECH];
    int b = blockIdx.x;
    int tid = threadIdx.x;
    int len = lengths[b];
    int ntiles = (len + TS - 1) / TS;
    if (tid < ZD) {
        float s = 0.f;
        for (int t = 0; t < ntiles; t++) s += g_zpart[(b * NTILES + t) * ZD + tid];
        z_b[tid] = s;
    }
    __syncthreads();
    float acc = b3[tid];
    #pragma unroll 8
    for (int k = 0; k < ZD; k++) acc = fmaf(z_b[k], W3[k * DECH + tid], acc);
    redc[tid] = fmaxf(acc, 0.f) * W4[tid];
    __syncthreads();
    #pragma unroll
    for (int o = DECH / 2; o > 0; o >>= 1) {
        if (tid < o) redc[tid] += redc[tid + o];
        __syncthreads();
    }
    if (tid == 0) y[b] = redc[0] + b4[0];
}

// ---------------------------------------------------------------------------
extern "C" void kernel_launch(void* const* d_in, const int* in_sizes, int n_in,
                              void* d_out, int out_size) {
    const float* u       = (const float*)d_in[0];
    const int*   lengths = (const int*)  d_in[1];
    const float* W1      = (const float*)d_in[2];
    const float* b1      = (const float*)d_in[3];
    const float* W2      = (const float*)d_in[4];
    const float* b2      = (const float*)d_in[5];
    const float* W3      = (const float*)d_in[6];
    const float* b3      = (const float*)d_in[7];
    const float* W4      = (const float*)d_in[8];
    const float* b4      = (const float*)d_in[9];
    float* y = (float*)d_out;

    static int smem_set = 0;
    if (!smem_set) {
        cudaFuncSetAttribute((const void*)main_kernel,
                             cudaFuncAttributeMaxDynamicSharedMemorySize, SMEM_SZ);
        smem_set = 1;
    }

    rowsum_kernel<<<2048, 256>>>(u, lengths);
    cvec_kernel<<<B_, ENCH>>>(W1, b1);
    prep_w1t<<<512, 256>>>(W1);
    prep_w2t<<<128, 256>>>(W2);

    dim3 grid(NTILES, B_);
    main_kernel<<<grid, 256, SMEM_SZ>>>(u, lengths, b2);

    tail_kernel<<<B_, DECH>>>(lengths, W3, b3, W4, b4, y);
}

// round 12
// speedup vs baseline: 9.5051x; 1.0482x over previous
#include <cuda_runtime.h>
#include <cuda_fp16.h>

typedef unsigned int u32;
typedef unsigned long long u64;

#define B_   64
#define NGF  256
#define S_   2048
#define ENCH 512
#define ZD   64
#define DECH 256
#define TS   128
#define NTILES 16

// ---- smem byte offsets ----
#define U_HI   0         // [256 g][128 s] fp16  64KB
#define A1_HI  65536     // [64 h][256 g] fp16   32KB
#define W2_HI  65536     // overlay on A1 (after GEMM1 done): [64 z][64 h] 8KB
#define HT_HI  98304     // [64 h][128 s] fp16   16KB
#define RED_O  114688    // 256 floats
#define SMEM_SZ 115712

__device__ float g_w[B_*NGF];
__device__ float g_c[B_*ENCH];
__device__ float g_zpart[B_*NTILES*ZD];
__device__ __half g_w1t[ENCH*NGF];   // [h][g] = fp16(W1[g][h])
__device__ __half g_w2t[ZD*ENCH];    // [z][h] = fp16(W2[h][z])

// ---- helpers ---------------------------------------------------------------
__device__ __forceinline__ u32 smem_u32(const void* p) {
    u32 a;
    asm("{ .reg .u64 t; cvta.to.shared.u64 t, %1; cvt.u32.u64 %0, t; }"
        : "=r"(a) : "l"(p));
    return a;
}
__device__ __forceinline__ void ldsm4(u32* r, u32 addr) {
    asm volatile("ldmatrix.sync.aligned.m8n8.x4.shared.b16 {%0,%1,%2,%3}, [%4];"
        : "=r"(r[0]), "=r"(r[1]), "=r"(r[2]), "=r"(r[3]) : "r"(addr));
}
__device__ __forceinline__ void ldsm4t(u32* r, u32 addr) {
    asm volatile("ldmatrix.sync.aligned.m8n8.x4.trans.shared.b16 {%0,%1,%2,%3}, [%4];"
        : "=r"(r[0]), "=r"(r[1]), "=r"(r[2]), "=r"(r[3]) : "r"(addr));
}
__device__ __forceinline__ void mma_h(float* c, const u32* a, u32 b0, u32 b1) {
    asm volatile("mma.sync.aligned.m16n8k16.row.col.f32.f16.f16.f32 "
        "{%0,%1,%2,%3}, {%4,%5,%6,%7}, {%8,%9}, {%0,%1,%2,%3};"
        : "+f"(c[0]), "+f"(c[1]), "+f"(c[2]), "+f"(c[3])
        : "r"(a[0]), "r"(a[1]), "r"(a[2]), "r"(a[3]), "r"(b0), "r"(b1));
}
__device__ __forceinline__ u32 packh2(float lo, float hi) {
    __half2 h = __floats2half2_rn(lo, hi);
    return *(u32*)&h;
}

// ---------------------------------------------------------------------------
// Fused prep kernel: grid sections.
//   blocks [0, 2048)        : rowsum  (one warp per (b,g) row)
//   blocks [2048, 2560)     : prep_w1t
//   blocks [2560, 2688)     : prep_w2t
// ---------------------------------------------------------------------------
__global__ void __launch_bounds__(256)
prep_all_kernel(const float* __restrict__ u, const int* __restrict__ lengths,
                const float* __restrict__ W1, const float* __restrict__ W2) {
    int bid = blockIdx.x;
    if (bid < 2048) {
        int warp = (bid * 256 + threadIdx.x) >> 5;     // 0 .. 16383
        int lane = threadIdx.x & 31;
        int b = warp >> 8;
        int len = lengths[b];
        const float* row = u + (size_t)warp * S_;
        float sum = 0.f;
        for (int s = lane; s < len; s += 32) sum += row[s];
        #pragma unroll
        for (int o = 16; o > 0; o >>= 1) sum += __shfl_down_sync(0xffffffffu, sum, o);
        if (lane == 0) g_w[warp] = sum;
    } else if (bid < 2560) {
        int idx = (bid - 2048) * 256 + threadIdx.x;    // 512*256
        int h = idx >> 8, g = idx & 255;
        g_w1t[h * NGF + g] = __float2half_rn(W1[(size_t)g * ENCH + h]);
    } else {
        int idx = (bid - 2560) * 256 + threadIdx.x;    // 64*512
        int z = idx >> 9, h = idx & 511;
        g_w2t[z * ENCH + h] = __float2half_rn(W2[(size_t)h * ZD + z]);
    }
}

// ---------------------------------------------------------------------------
// cvec: c[b,h] = b1[h] + sum_g w[b,g] * W1[256+g, h]
// ---------------------------------------------------------------------------
__global__ void cvec_kernel(const float* __restrict__ W1,
                            const float* __restrict__ b1) {
    __shared__ float wsh[NGF];
    int b = blockIdx.x;
    int h = threadIdx.x;          // 512 threads
    if (h < NGF) wsh[h] = g_w[b * NGF + h];
    __syncthreads();
    float acc = b1[h];
    const float* Wp = W1 + (size_t)NGF * ENCH + h;
    #pragma unroll 8
    for (int g = 0; g < NGF; g++) acc = fmaf(wsh[g], Wp[(size_t)g * ENCH], acc);
    g_c[b * ENCH + h] = acc;
}

// ---------------------------------------------------------------------------
// Main HMMA kernel: per (b, 128-s tile). 256 threads = 8 warps (2m x 4n),
// warp tile m32 x n32. Pure fp16 operands, fp32 accumulate. 2 CTAs/SM.
// ---------------------------------------------------------------------------
__global__ void __launch_bounds__(256, 2)
main_kernel(const float* __restrict__ u, const int* __restrict__ lengths,
            const float* __restrict__ b2) {
    extern __shared__ char smem[];
    u32 sb = smem_u32(smem);
    int b = blockIdx.y, tile = blockIdx.x;
    int len = lengths[b];
    int s0 = tile * TS;
    if (s0 >= len) return;

    int tid = threadIdx.x;
    int lane = tid & 31;
    int wq = tid >> 5;         // 0..7
    int wm = wq >> 2;          // 0..1  (m: 32 rows each)
    int wn = wq & 3;           // 0..3  (n: 32 s cols each)
    int gid = lane >> 2, tq = lane & 3;
    int l16 = lane & 15;
    int asel = lane >> 4;

    // ---- load u tile fp32 -> fp16, [g][s] swizzled ----
    const float* ub = u + ((size_t)b * NGF) * S_ + s0;
    #pragma unroll 4
    for (int it = 0; it < 32; it++) {
        int i = tid + 256 * it;
        int g = i >> 5, q = i & 31;
        float4 v = *(const float4*)(ub + (size_t)g * S_ + q * 4);
        u32 off = (u32)(g * 256 + (((q >> 1) ^ (g & 7)) << 4) + ((q & 1) << 3));
        *(uint2*)(smem + U_HI + off) = make_uint2(packh2(v.x, v.y), packh2(v.z, v.w));
    }
    __syncthreads();

    float zc[2][4][4];
    #pragma unroll
    for (int mt = 0; mt < 2; mt++)
        #pragma unroll
        for (int j = 0; j < 4; j++)
            #pragma unroll
            for (int r = 0; r < 4; r++) zc[mt][j][r] = 0.f;

    const float* cb = g_c + b * ENCH;

    for (int hc = 0; hc < 8; hc++) {
        // ---- load A1 slice (W1T rows hc*64..+63, all 256 g) ----
        #pragma unroll
        for (int it = 0; it < 8; it++) {
            int idx = tid + 256 * it;          // 2048 uint4
            int h = idx >> 5, c = idx & 31;
            u32 off = (u32)(h * 512 + ((c ^ (h & 7)) << 4));
            *(uint4*)(smem + A1_HI + off) =
                *(const uint4*)(g_w1t + ((size_t)(hc * 64 + h)) * NGF + c * 8);
        }
        __syncthreads();

        float hacc[2][4][4];
        #pragma unroll
        for (int mt = 0; mt < 2; mt++)
            #pragma unroll
            for (int j = 0; j < 4; j++)
                #pragma unroll
                for (int r = 0; r < 4; r++) hacc[mt][j][r] = 0.f;

        // ---- GEMM1: K = 256 (16 k16-steps), m32n32 per warp, 8 MMA/step ----
        #pragma unroll 4
        for (int k = 0; k < 16; k++) {
            u32 ah[2][4], bh[2][4];
            #pragma unroll
            for (int mt = 0; mt < 2; mt++) {
                int arow = 32 * wm + 16 * mt + l16;
                u32 ach = (u32)(((2 * k + asel) ^ (arow & 7)) << 4);
                ldsm4(ah[mt], sb + A1_HI + arow * 512 + ach);
            }
            int brow = 16 * k + l16;
            #pragma unroll
            for (int j = 0; j < 2; j++) {
                u32 bc = (u32)(((4 * wn + 2 * j + asel) ^ (brow & 7)) << 4);
                ldsm4t(bh[j], sb + U_HI + (u32)(brow * 256) + bc);
            }
            #pragma unroll
            for (int mt = 0; mt < 2; mt++)
                #pragma unroll
                for (int j = 0; j < 2; j++) {
                    mma_h(hacc[mt][2 * j],     ah[mt], bh[j][0], bh[j][1]);
                    mma_h(hacc[mt][2 * j + 1], ah[mt], bh[j][2], bh[j][3]);
                }
        }
        __syncthreads();   // all warps done reading A1 before W2 overlay

        // ---- epilogue: bias+relu, fp16, store H^T [hloc][s] ----
        #pragma unroll
        for (int mt = 0; mt < 2; mt++) {
            int hl0 = 32 * wm + 16 * mt + gid, hl1 = hl0 + 8;
            float bia0 = cb[hc * 64 + hl0], bia1 = cb[hc * 64 + hl1];
            #pragma unroll
            for (int j = 0; j < 4; j++) {
                int sbse = wn * 32 + j * 8;
                float v00 = fmaxf(hacc[mt][j][0] + bia0, 0.f);
                float v01 = fmaxf(hacc[mt][j][1] + bia0, 0.f);
                float v10 = fmaxf(hacc[mt][j][2] + bia1, 0.f);
                float v11 = fmaxf(hacc[mt][j][3] + bia1, 0.f);
                u32 off0 = (u32)(hl0 * 256 + (((sbse >> 3) ^ (hl0 & 7)) << 4) + 4 * tq);
                *(u32*)(smem + HT_HI + off0) = packh2(v00, v01);
                u32 off1 = (u32)(hl1 * 256 + (((sbse >> 3) ^ (hl1 & 7)) << 4) + 4 * tq);
                *(u32*)(smem + HT_HI + off1) = packh2(v10, v11);
            }
        }
        // ---- load W2T slice [64 z][64 h-chunk] (overlay) ----
        #pragma unroll
        for (int it = 0; it < 2; it++) {
            int idx = tid + 256 * it;          // 512 uint4
            int z = idx >> 3, c = idx & 7;
            u32 off = (u32)(z * 128 + ((c ^ (z & 7)) << 4));
            *(uint4*)(smem + W2_HI + off) =
                *(const uint4*)(g_w2t + (size_t)z * ENCH + hc * 64 + c * 8);
        }
        __syncthreads();

        // ---- GEMM2 partial: K = 64 (4 k16-steps), 8 MMA/step ----
        #pragma unroll
        for (int k2 = 0; k2 < 4; k2++) {
            u32 ah[2][4], bh[2][4];
            #pragma unroll
            for (int mt = 0; mt < 2; mt++) {
                int arow = 32 * wm + 16 * mt + l16;
                u32 ach = (u32)(((2 * k2 + asel) ^ (arow & 7)) << 4);
                ldsm4(ah[mt], sb + W2_HI + arow * 128 + ach);
            }
            int brow = 16 * k2 + l16;
            #pragma unroll
            for (int j = 0; j < 2; j++) {
                u32 bc = (u32)(((4 * wn + 2 * j + asel) ^ (brow & 7)) << 4);
                ldsm4t(bh[j], sb + HT_HI + (u32)(brow * 256) + bc);
            }
            #pragma unroll
            for (int mt = 0; mt < 2; mt++)
                #pragma unroll
                for (int j = 0; j < 2; j++) {
                    mma_h(zc[mt][2 * j],     ah[mt], bh[j][0], bh[j][1]);
                    mma_h(zc[mt][2 * j + 1], ah[mt], bh[j][2], bh[j][3]);
                }
        }
        __syncthreads();   // Ht/W2 consumed; safe to overwrite next chunk
    }

    // ---- final: bias+relu+mask, reduce over s ----
    float* red = (float*)(smem + RED_O);
    #pragma unroll
    for (int mt = 0; mt < 2; mt++) {
        int z0 = 32 * wm + 16 * mt + gid, z1 = z0 + 8;
        float bz0 = b2[z0], bz1 = b2[z1];
        float p0 = 0.f, p1 = 0.f;
        #pragma unroll
        for (int j = 0; j < 4; j++) {
            int sa = s0 + wn * 32 + j * 8 + 2 * tq;
            if (sa < len) {
                p0 += fmaxf(zc[mt][j][0] + bz0, 0.f);
                p1 += fmaxf(zc[mt][j][2] + bz1, 0.f);
            }
            if (sa + 1 < len) {
                p0 += fmaxf(zc[mt][j][1] + bz0, 0.f);
                p1 += fmaxf(zc[mt][j][3] + bz1, 0.f);
            }
        }
        p0 += __shfl_xor_sync(0xffffffffu, p0, 1);
        p0 += __shfl_xor_sync(0xffffffffu, p0, 2);
        p1 += __shfl_xor_sync(0xffffffffu, p1, 1);
        p1 += __shfl_xor_sync(0xffffffffu, p1, 2);
        if (tq == 0) {
            red[wn * 64 + z0] = p0;
            red[wn * 64 + z1] = p1;
        }
    }
    __syncthreads();
    if (tid < ZD) {
        float s = 0.f;
        #pragma unroll
        for (int wnn = 0; wnn < 4; wnn++) s += red[wnn * 64 + tid];
        g_zpart[(b * NTILES + tile) * ZD + tid] = s;
    }
}

// ---------------------------------------------------------------------------
// Tail: z = sum of partials; d = relu(z@W3+b3); y = d@W4 + b4.
// ---------------------------------------------------------------------------
__global__ void tail_kernel(const int* __restrict__ lengths,
                            const float* __restrict__ W3, const float* __restrict__ b3,
                            const float* __restrict__ W4, const float* __restrict__ b4,
                            float* __restrict__ y) {
    __shared__ float z_b[ZD];
    __shared__ float redc[DECH];
    int b = blockIdx.x;
    int tid = threadIdx.x;
    int len = lengths[b];
    int ntiles = (len + TS - 1) / TS;
    if (tid < ZD) {
        float s = 0.f;
        for (int t = 0; t < ntiles; t++) s += g_zpart[(b * NTILES + t) * ZD + tid];
        z_b[tid] = s;
    }
    __syncthreads();
    float acc = b3[tid];
    #pragma unroll 8
    for (int k = 0; k < ZD; k++) acc = fmaf(z_b[k], W3[k * DECH + tid], acc);
    redc[tid] = fmaxf(acc, 0.f) * W4[tid];
    __syncthreads();
    #pragma unroll
    for (int o = DECH / 2; o > 0; o >>= 1) {
        if (tid < o) redc[tid] += redc[tid + o];
        __syncthreads();
    }
    if (tid == 0) y[b] = redc[0] + b4[0];
}

// ---------------------------------------------------------------------------
extern "C" void kernel_launch(void* const* d_in, const int* in_sizes, int n_in,
                              void* d_out, int out_size) {
    const float* u       = (const float*)d_in[0];
    const int*   lengths = (const int*)  d_in[1];
    const float* W1      = (const float*)d_in[2];
    const float* b1      = (const float*)d_in[3];
    const float* W2      = (const float*)d_in[4];
    const float* b2      = (const float*)d_in[5];
    const float* W3      = (const float*)d_in[6];
    const float* b3      = (const float*)d_in[7];
    const float* W4      = (const float*)d_in[8];
    const float* b4      = (const float*)d_in[9];
    float* y = (float*)d_out;

    static int smem_set = 0;
    if (!smem_set) {
        cudaFuncSetAttribute((const void*)main_kernel,
                             cudaFuncAttributeMaxDynamicSharedMemorySize, SMEM_SZ);
        smem_set = 1;
    }

    prep_all_kernel<<<2688, 256>>>(u, lengths, W1, W2);
    cvec_kernel<<<B_, ENCH>>>(W1, b1);

    dim3 grid(NTILES, B_);
    main_kernel<<<grid, 256, SMEM_SZ>>>(u, lengths, b2);

    tail_kernel<<<B_, DECH>>>(lengths, W3, b3, W4, b4, y);
}